// round 9
// baseline (speedup 1.0000x reference)
#include <cuda_runtime.h>
#include <cuda_bf16.h>
#include <cstdint>

#define MTOT   32768
#define DMODEL 512
#define HID2   1024
#define NRELS  2048
#define CAND   32
#define STAGE_B 32768                 // A tile 16KB + B tile 16KB
#define GSMEM  (3 * STAGE_B)          // 3 stages = 96KB -> 2 CTAs/SM

// ---------------- scratch (static device globals; no allocs) ----------------
__device__ float          g_Wc[DMODEL * DMODEL];
__device__ float          g_bc[DMODEL];
__device__ __nv_bfloat16  g_xh[MTOT * DMODEL],  g_xl[MTOT * DMODEL];
__device__ __nv_bfloat16  g_Wch[DMODEL * DMODEL], g_Wcl[DMODEL * DMODEL];
__device__ __nv_bfloat16  g_w1h[HID2 * DMODEL],  g_w1l[HID2 * DMODEL];
__device__ float          g_attn[MTOT * DMODEL];
__device__ __nv_bfloat16  g_hh[MTOT * DMODEL],  g_hl[MTOT * DMODEL];
__device__ float          g_gactf[MTOT * HID2];
__device__ int8_t         g_gact8[MTOT * HID2];
__device__ int8_t         g_w28[NRELS * HID2];
__device__ __nv_bfloat16  g_logits[MTOT * NRELS];
__device__ float          g_m[2][MTOT];
__device__ int            g_idx[2][MTOT];
__device__ int            g_cnt[MTOT];
__device__ int            g_cand[MTOT * CAND];
__device__ float          g_scales[3];        // [0]=wmax, [1]=gmax step0, [2]=gmax step1

// ---------------- PTX helpers (baseline ISA only) ----------------
__device__ __forceinline__ uint32_t smem_u32(const void* p) {
    uint32_t a;
    asm("{ .reg .u64 t; cvta.to.shared.u64 t, %1; cvt.u32.u64 %0, t; }" : "=r"(a) : "l"(p));
    return a;
}

#define CP_ASYNC16(sp, gp) \
    asm volatile("cp.async.cg.shared.global [%0], [%1], 16;\n" :: "r"(sp), "l"(gp) : "memory")
#define CP_COMMIT()   asm volatile("cp.async.commit_group;\n" ::: "memory")
#define CP_WAIT1()    asm volatile("cp.async.wait_group 1;\n" ::: "memory")

#define LDSM_X4(r, addr) \
    asm volatile("ldmatrix.sync.aligned.m8n8.x4.shared.b16 {%0,%1,%2,%3}, [%4];" \
        : "=r"((r)[0]), "=r"((r)[1]), "=r"((r)[2]), "=r"((r)[3]) : "r"(addr))

__device__ __forceinline__ void mma16816(float* c, const uint32_t* a, uint32_t b0, uint32_t b1) {
    asm volatile(
        "mma.sync.aligned.m16n8k16.row.col.f32.bf16.bf16.f32 "
        "{%0,%1,%2,%3},{%4,%5,%6,%7},{%8,%9},{%0,%1,%2,%3};\n"
        : "+f"(c[0]), "+f"(c[1]), "+f"(c[2]), "+f"(c[3])
        : "r"(a[0]), "r"(a[1]), "r"(a[2]), "r"(a[3]), "r"(b0), "r"(b1));
}

__device__ __forceinline__ void mma16832s8(int* c, const uint32_t* a, uint32_t b0, uint32_t b1) {
    asm volatile(
        "mma.sync.aligned.m16n8k32.row.col.s32.s8.s8.s32 "
        "{%0,%1,%2,%3},{%4,%5,%6,%7},{%8,%9},{%0,%1,%2,%3};\n"
        : "+r"(c[0]), "+r"(c[1]), "+r"(c[2]), "+r"(c[3])
        : "r"(a[0]), "r"(a[1]), "r"(a[2]), "r"(a[3]), "r"(b0), "r"(b1));
}

// ldmatrix address into a (rows x 128B) tile, xor-swizzled 16B chunks
__device__ __forceinline__ uint32_t ldsm_addr(uint32_t base, int row0, int chunk0, int lane) {
    const int r = row0 + (lane & 15);
    const int c = chunk0 + (lane >> 4);
    return base + r * 128 + ((c ^ (r & 7)) << 4);
}

// ---------------- bf16 HMMA GEMM: C[M,N] = sum_reg A_reg @ B_reg^T (+bias) ---
// CTA 128x128, 8 warps (2x4), warp tile 64x32, K-tile 64, 3-stage cp.async.
// EPI 0: Cf fp32      EPI 1: relu -> Cf fp32 + tensor absmax into gmaxi
template <int EPI>
__global__ __launch_bounds__(256, 2) void mma_gemm(
    const __nv_bfloat16* __restrict__ A0, const __nv_bfloat16* __restrict__ A1,
    const __nv_bfloat16* __restrict__ A2, const __nv_bfloat16* __restrict__ A3,
    const __nv_bfloat16* __restrict__ B0, const __nv_bfloat16* __restrict__ B1,
    const __nv_bfloat16* __restrict__ B2, const __nv_bfloat16* __restrict__ B3,
    const float* __restrict__ bias, float* __restrict__ Cf, int* __restrict__ gmaxi,
    int N, int Kreg, int kcpr, int nch)
{
    extern __shared__ __align__(1024) char sm[];
    const int tid  = threadIdx.x;
    const int wid  = tid >> 5;
    const int lane = tid & 31;
    const int bm   = blockIdx.y * 128;
    const int bn   = blockIdx.x * 128;
    const int wm   = (wid >> 2) * 64;
    const int wn   = (wid & 3) * 32;

    const uint32_t sBase = smem_u32(sm);

    float acc[4][4][4];
#pragma unroll
    for (int i = 0; i < 4; i++)
#pragma unroll
        for (int j = 0; j < 4; j++)
#pragma unroll
            for (int k = 0; k < 4; k++) acc[i][j][k] = 0.f;

    auto load_tile = [&](int c, int stage) {
        const int reg = c / kcpr;
        const int kc  = c - reg * kcpr;
        const __nv_bfloat16* Ar = (reg == 0) ? A0 : (reg == 1) ? A1 : (reg == 2) ? A2 : A3;
        const __nv_bfloat16* Br = (reg == 0) ? B0 : (reg == 1) ? B1 : (reg == 2) ? B2 : B3;
        const uint32_t aBase = sBase + stage * STAGE_B;
        const uint32_t bBase = aBase + 16384;
#pragma unroll
        for (int i = 0; i < 4; i++) {
            const int u = tid + 256 * i;
            const int r = u >> 3, ch = u & 7;
            const uint32_t soff = r * 128 + ((ch ^ (r & 7)) << 4);
            CP_ASYNC16(aBase + soff, Ar + (size_t)(bm + r) * Kreg + kc * 64 + ch * 8);
            CP_ASYNC16(bBase + soff, Br + (size_t)(bn + r) * Kreg + kc * 64 + ch * 8);
        }
    };

    load_tile(0, 0); CP_COMMIT();
    load_tile(1, 1); CP_COMMIT();

    int stage = 0;
    for (int c = 0; c < nch; c++) {
        CP_WAIT1();
        __syncthreads();
        if (c + 2 < nch) load_tile(c + 2, (c + 2) % 3);
        CP_COMMIT();

        const uint32_t aB = sBase + stage * STAGE_B;
        const uint32_t bB = aB + 16384;
#pragma unroll
        for (int kk = 0; kk < 4; kk++) {
            uint32_t ar[4][4], br[2][4];
#pragma unroll
            for (int mt = 0; mt < 4; mt++)
                LDSM_X4(ar[mt], ldsm_addr(aB, wm + mt * 16, 2 * kk, lane));
#pragma unroll
            for (int nt = 0; nt < 2; nt++)
                LDSM_X4(br[nt], ldsm_addr(bB, wn + nt * 16, 2 * kk, lane));
#pragma unroll
            for (int mt = 0; mt < 4; mt++)
#pragma unroll
                for (int j = 0; j < 4; j++)
                    mma16816(acc[mt][j], ar[mt], br[j >> 1][j & 1], br[j >> 1][(j & 1) + 2]);
        }
        stage = (stage + 1) == 3 ? 0 : (stage + 1);
    }

    // ---- epilogue ----
    const int rbase = bm + wm + (lane >> 2);
    const int cbase = bn + wn + ((lane & 3) << 1);
    float tmax = 0.f;
#pragma unroll
    for (int mt = 0; mt < 4; mt++) {
#pragma unroll
        for (int j = 0; j < 4; j++) {
            const int row = rbase + mt * 16;
            const int col = cbase + j * 8;
            const float b0 = __ldg(&bias[col]), b1 = __ldg(&bias[col + 1]);
            float v0 = acc[mt][j][0] + b0, v1 = acc[mt][j][1] + b1;
            float v2 = acc[mt][j][2] + b0, v3 = acc[mt][j][3] + b1;
            if (EPI == 1) {
                v0 = fmaxf(v0, 0.f); v1 = fmaxf(v1, 0.f);
                v2 = fmaxf(v2, 0.f); v3 = fmaxf(v3, 0.f);
                tmax = fmaxf(tmax, fmaxf(fmaxf(v0, v1), fmaxf(v2, v3)));
            }
            *(float2*)(Cf + (size_t)row * N + col)       = make_float2(v0, v1);
            *(float2*)(Cf + (size_t)(row + 8) * N + col) = make_float2(v2, v3);
        }
    }
    if (EPI == 1) {
#pragma unroll
        for (int o = 16; o; o >>= 1) tmax = fmaxf(tmax, __shfl_xor_sync(0xffffffffu, tmax, o));
        if (lane == 0) atomicMax(gmaxi, __float_as_int(tmax));   // gact >= 0
    }
}

// ---------------- int8 IMMA GEMM: logits(bf16) = (A8 @ B8^T)*scale + bias ----
// CTA 128x128, warp 64x32, K-tile 128 int8, 3-stage. K = HID2 bytes per row.
__global__ __launch_bounds__(256, 2) void mma_gemm_s8(
    const int8_t* __restrict__ A, const int8_t* __restrict__ B,
    const float* __restrict__ bias, const float* __restrict__ gmaxp,
    const float* __restrict__ wmaxp, __nv_bfloat16* __restrict__ Cb,
    int N, int K, int nch)
{
    extern __shared__ __align__(1024) char sm[];
    const int tid  = threadIdx.x;
    const int wid  = tid >> 5;
    const int lane = tid & 31;
    const int bm   = blockIdx.y * 128;
    const int bn   = blockIdx.x * 128;
    const int wm   = (wid >> 2) * 64;
    const int wn   = (wid & 3) * 32;

    const uint32_t sBase = smem_u32(sm);

    int acc[4][4][4];
#pragma unroll
    for (int i = 0; i < 4; i++)
#pragma unroll
        for (int j = 0; j < 4; j++)
#pragma unroll
            for (int k = 0; k < 4; k++) acc[i][j][k] = 0;

    auto load_tile = [&](int kc, int stage) {
        const uint32_t aBase = sBase + stage * STAGE_B;
        const uint32_t bBase = aBase + 16384;
#pragma unroll
        for (int i = 0; i < 4; i++) {
            const int u = tid + 256 * i;            // 128 rows x 8 chunks of 16B
            const int r = u >> 3, ch = u & 7;
            const uint32_t soff = r * 128 + ((ch ^ (r & 7)) << 4);
            CP_ASYNC16(aBase + soff, A + (size_t)(bm + r) * K + kc * 128 + ch * 16);
            CP_ASYNC16(bBase + soff, B + (size_t)(bn + r) * K + kc * 128 + ch * 16);
        }
    };

    load_tile(0, 0); CP_COMMIT();
    load_tile(1, 1); CP_COMMIT();

    int stage = 0;
    for (int c = 0; c < nch; c++) {
        CP_WAIT1();
        __syncthreads();
        if (c + 2 < nch) load_tile(c + 2, (c + 2) % 3);
        CP_COMMIT();

        const uint32_t aB = sBase + stage * STAGE_B;
        const uint32_t bB = aB + 16384;
#pragma unroll
        for (int kk = 0; kk < 4; kk++) {             // 4 x k32 = 128 int8
            uint32_t ar[4][4], br[2][4];
#pragma unroll
            for (int mt = 0; mt < 4; mt++)
                LDSM_X4(ar[mt], ldsm_addr(aB, wm + mt * 16, 2 * kk, lane));
#pragma unroll
            for (int nt = 0; nt < 2; nt++)
                LDSM_X4(br[nt], ldsm_addr(bB, wn + nt * 16, 2 * kk, lane));
#pragma unroll
            for (int mt = 0; mt < 4; mt++)
#pragma unroll
                for (int j = 0; j < 4; j++)
                    mma16832s8(acc[mt][j], ar[mt], br[j >> 1][j & 1], br[j >> 1][(j & 1) + 2]);
        }
        stage = (stage + 1) == 3 ? 0 : (stage + 1);
    }

    // ---- epilogue: dequant + bias -> bf16 ----
    const float scale = (*gmaxp) * (*wmaxp) * (1.f / (127.f * 127.f));
    const int rbase = bm + wm + (lane >> 2);
    const int cbase = bn + wn + ((lane & 3) << 1);
#pragma unroll
    for (int mt = 0; mt < 4; mt++) {
#pragma unroll
        for (int j = 0; j < 4; j++) {
            const int row = rbase + mt * 16;
            const int col = cbase + j * 8;
            const float b0 = __ldg(&bias[col]), b1 = __ldg(&bias[col + 1]);
            float v0 = (float)acc[mt][j][0] * scale + b0;
            float v1 = (float)acc[mt][j][1] * scale + b1;
            float v2 = (float)acc[mt][j][2] * scale + b0;
            float v3 = (float)acc[mt][j][3] * scale + b1;
            *(__nv_bfloat162*)(Cb + (size_t)row * N + col)       = __floats2bfloat162_rn(v0, v1);
            *(__nv_bfloat162*)(Cb + (size_t)(row + 8) * N + col) = __floats2bfloat162_rn(v2, v3);
        }
    }
}

// ---------------- small prep kernels ----------------
__global__ void zero_scales_kernel() {
    if (threadIdx.x < 3) g_scales[threadIdx.x] = 0.f;
}

__global__ void absmax_kernel(const float* __restrict__ src, int n, int* __restrict__ outm)
{
    const int lane = threadIdx.x & 31;
    float m = 0.f;
    for (int i = blockIdx.x * blockDim.x + threadIdx.x; i < n; i += gridDim.x * blockDim.x)
        m = fmaxf(m, fabsf(src[i]));
#pragma unroll
    for (int o = 16; o; o >>= 1) m = fmaxf(m, __shfl_xor_sync(0xffffffffu, m, o));
    if (lane == 0) atomicMax(outm, __float_as_int(m));
}

// fp32 -> int8 with scale max/127 (4 elems/thread)
__global__ void quant_kernel(const float* __restrict__ src, int8_t* __restrict__ dst,
                             const float* __restrict__ maxp, int n4)
{
    const int i = blockIdx.x * blockDim.x + threadIdx.x;
    if (i >= n4) return;
    const float si = 127.f / fmaxf(*maxp, 1e-20f);
    float4 v = ((const float4*)src)[i];
    int q0 = max(-127, min(127, __float2int_rn(v.x * si)));
    int q1 = max(-127, min(127, __float2int_rn(v.y * si)));
    int q2 = max(-127, min(127, __float2int_rn(v.z * si)));
    int q3 = max(-127, min(127, __float2int_rn(v.w * si)));
    ((char4*)dst)[i] = make_char4((char)q0, (char)q1, (char)q2, (char)q3);
}

__global__ void combine_w_kernel(const float* __restrict__ ow, const float* __restrict__ vw,
                                 float* __restrict__ wc)
{
    __shared__ float As[16][16];
    __shared__ float Bs[16][17];
    const int tx = threadIdx.x, ty = threadIdx.y;
    const int i = blockIdx.y * 16 + ty;
    const int j = blockIdx.x * 16 + tx;
    float acc = 0.f;
    for (int k0 = 0; k0 < DMODEL; k0 += 16) {
        As[ty][tx] = ow[i * DMODEL + k0 + tx];
        Bs[ty][tx] = vw[(k0 + ty) * DMODEL + j];
        __syncthreads();
#pragma unroll
        for (int kk = 0; kk < 16; kk++) acc = fmaf(As[ty][kk], Bs[kk][tx], acc);
        __syncthreads();
    }
    wc[i * DMODEL + j] = acc;
}

__global__ void combine_b_kernel(const float* __restrict__ ow, const float* __restrict__ vb,
                                 const float* __restrict__ ob, float* __restrict__ bc)
{
    const int i = threadIdx.x;
    float acc = 0.f;
    for (int k = 0; k < DMODEL; k++) acc = fmaf(ow[i * DMODEL + k], vb[k], acc);
    bc[i] = acc + ob[i];
}

// fp32 -> (bf16 hi, bf16 lo) split, 4 elems / thread
__global__ void split_kernel(const float* __restrict__ in, __nv_bfloat16* __restrict__ hi,
                             __nv_bfloat16* __restrict__ lo, int n4)
{
    const int i = blockIdx.x * blockDim.x + threadIdx.x;
    if (i >= n4) return;
    float4 v = ((const float4*)in)[i];
    __nv_bfloat16 h0 = __float2bfloat16_rn(v.x), h1 = __float2bfloat16_rn(v.y);
    __nv_bfloat16 h2 = __float2bfloat16_rn(v.z), h3 = __float2bfloat16_rn(v.w);
    __nv_bfloat16 l0 = __float2bfloat16_rn(v.x - __bfloat162float(h0));
    __nv_bfloat16 l1 = __float2bfloat16_rn(v.y - __bfloat162float(h1));
    __nv_bfloat16 l2 = __float2bfloat16_rn(v.z - __bfloat162float(h2));
    __nv_bfloat16 l3 = __float2bfloat16_rn(v.w - __bfloat162float(h3));
    __nv_bfloat162* H = (__nv_bfloat162*)hi;
    __nv_bfloat162* L = (__nv_bfloat162*)lo;
    H[2 * i] = __nv_bfloat162(h0, h1); H[2 * i + 1] = __nv_bfloat162(h2, h3);
    L[2 * i] = __nv_bfloat162(l0, l1); L[2 * i + 1] = __nv_bfloat162(l2, l3);
}

// ---------------- LayerNorm(attn + state) -> split bf16 planes --------------
__global__ __launch_bounds__(256) void ln_kernel(
    const float* __restrict__ attn, const float* __restrict__ state, int sstride,
    const float* __restrict__ gamma, const float* __restrict__ beta,
    __nv_bfloat16* __restrict__ hh, __nv_bfloat16* __restrict__ hl)
{
    const int warp = threadIdx.x >> 5, lane = threadIdx.x & 31;
    const int row = blockIdx.x * 8 + warp;
    const float4* ap = (const float4*)(attn + (size_t)row * DMODEL);
    const float4* sp = (const float4*)(state + (size_t)row * sstride);

    float v[16];
    float s = 0.f, ss = 0.f;
#pragma unroll
    for (int q = 0; q < 4; q++) {
        float4 a = ap[lane + 32 * q];
        float4 st = sp[lane + 32 * q];
        float x0 = a.x + st.x, x1 = a.y + st.y, x2 = a.z + st.z, x3 = a.w + st.w;
        v[4 * q] = x0; v[4 * q + 1] = x1; v[4 * q + 2] = x2; v[4 * q + 3] = x3;
        s += x0 + x1 + x2 + x3;
        ss += x0 * x0 + x1 * x1 + x2 * x2 + x3 * x3;
    }
#pragma unroll
    for (int o = 16; o; o >>= 1) {
        s  += __shfl_xor_sync(0xffffffffu, s, o);
        ss += __shfl_xor_sync(0xffffffffu, ss, o);
    }
    const float mean = s * (1.f / DMODEL);
    const float var  = ss * (1.f / DMODEL) - mean * mean;
    const float inv  = rsqrtf(var + 1e-5f);

    const float4* gp = (const float4*)gamma;
    const float4* bp = (const float4*)beta;
    uint2* hp = (uint2*)(hh + (size_t)row * DMODEL);
    uint2* lp = (uint2*)(hl + (size_t)row * DMODEL);
#pragma unroll
    for (int q = 0; q < 4; q++) {
        float4 g = gp[lane + 32 * q], b = bp[lane + 32 * q];
        float o0 = (v[4 * q] - mean) * inv * g.x + b.x;
        float o1 = (v[4 * q + 1] - mean) * inv * g.y + b.y;
        float o2 = (v[4 * q + 2] - mean) * inv * g.z + b.z;
        float o3 = (v[4 * q + 3] - mean) * inv * g.w + b.w;
        __nv_bfloat16 h0 = __float2bfloat16_rn(o0), h1 = __float2bfloat16_rn(o1);
        __nv_bfloat16 h2 = __float2bfloat16_rn(o2), h3 = __float2bfloat16_rn(o3);
        __nv_bfloat162 ph0(h0, h1), ph1(h2, h3);
        __nv_bfloat162 pl0(__float2bfloat16_rn(o0 - __bfloat162float(h0)),
                           __float2bfloat16_rn(o1 - __bfloat162float(h1)));
        __nv_bfloat162 pl1(__float2bfloat16_rn(o2 - __bfloat162float(h2)),
                           __float2bfloat16_rn(o3 - __bfloat162float(h3)));
        hp[lane + 32 * q] = make_uint2(*(uint32_t*)&ph0, *(uint32_t*)&ph1);
        lp[lane + 32 * q] = make_uint2(*(uint32_t*)&pl0, *(uint32_t*)&pl1);
    }
}

// --------- per-row: max / 1/sumexp / candidate set from bf16 logits ---------
__device__ __forceinline__ float2 bf2f2(uint32_t w) {
    float2 r;
    r.x = __uint_as_float(w << 16);
    r.y = __uint_as_float(w & 0xffff0000u);
    return r;
}

__global__ __launch_bounds__(256) void reduce2_kernel(
    const __nv_bfloat16* __restrict__ logits, float* __restrict__ mOut,
    int* __restrict__ cnt, int* __restrict__ cand)
{
    __shared__ int scnt[8];
    const int warp = threadIdx.x >> 5, lane = threadIdx.x & 31;
    const int row = blockIdx.x * 8 + warp;
    const uint4* lp = (const uint4*)(logits + (size_t)row * NRELS);

    float vmax = -3.4e38f;
#pragma unroll
    for (int q = 0; q < 8; q++) {
        uint4 u = lp[lane + 32 * q];
        float2 a = bf2f2(u.x), b = bf2f2(u.y), c = bf2f2(u.z), d = bf2f2(u.w);
        vmax = fmaxf(vmax, fmaxf(fmaxf(fmaxf(a.x, a.y), fmaxf(b.x, b.y)),
                                 fmaxf(fmaxf(c.x, c.y), fmaxf(d.x, d.y))));
    }
#pragma unroll
    for (int o = 16; o; o >>= 1) vmax = fmaxf(vmax, __shfl_xor_sync(0xffffffffu, vmax, o));

    if (lane == 0) scnt[warp] = 0;
    __syncwarp();

    const float thr = vmax - 0.05f;      // covers int8 quant noise (~4e-3 sigma)
    float se = 0.f;
#pragma unroll
    for (int q = 0; q < 8; q++) {
        uint4 u = lp[lane + 32 * q];
        uint32_t ws[4] = {u.x, u.y, u.z, u.w};
        const int base = (lane + 32 * q) * 8;
#pragma unroll
        for (int wI = 0; wI < 4; wI++) {
            float2 e = bf2f2(ws[wI]);
            se += __expf(e.x - vmax) + __expf(e.y - vmax);
            if (e.x >= thr) {
                int p = atomicAdd(&scnt[warp], 1);
                if (p < CAND) cand[(size_t)row * CAND + p] = base + 2 * wI;
            }
            if (e.y >= thr) {
                int p = atomicAdd(&scnt[warp], 1);
                if (p < CAND) cand[(size_t)row * CAND + p] = base + 2 * wI + 1;
            }
        }
    }
#pragma unroll
    for (int o = 16; o; o >>= 1) se += __shfl_xor_sync(0xffffffffu, se, o);
    __syncwarp();
    if (lane == 0) { mOut[row] = 1.f / se; cnt[row] = scnt[warp]; }
}

// --------- exact fp32 rescue of the argmax among candidates ---------
__global__ __launch_bounds__(256) void rescue_kernel(
    const float* __restrict__ gact, const float* __restrict__ w2,
    const float* __restrict__ b2, const int* __restrict__ cnt,
    const int* __restrict__ cand, int* __restrict__ idxOut)
{
    const int warp = threadIdx.x >> 5, lane = threadIdx.x & 31;
    const int row = blockIdx.x * 8 + warp;
    const float* g = gact + (size_t)row * HID2;
    const int n = cnt[row];

    float best = -3.4e38f;
    int bi = 0x7fffffff;
    if (n <= CAND) {
        for (int t = 0; t < n; t++) {
            const int j = cand[(size_t)row * CAND + t];
            const float* wr = w2 + (size_t)j * HID2;
            float s = 0.f;
            for (int k = lane; k < HID2; k += 32) s = fmaf(wr[k], g[k], s);
#pragma unroll
            for (int o = 16; o; o >>= 1) s += __shfl_xor_sync(0xffffffffu, s, o);
            s += b2[j];
            if (s > best || (s == best && j < bi)) { best = s; bi = j; }
        }
    } else {
        for (int j = 0; j < NRELS; j++) {
            const float* wr = w2 + (size_t)j * HID2;
            float s = 0.f;
            for (int k = lane; k < HID2; k += 32) s = fmaf(wr[k], g[k], s);
#pragma unroll
            for (int o = 16; o; o >>= 1) s += __shfl_xor_sync(0xffffffffu, s, o);
            s += b2[j];
            if (s > best || (s == best && j < bi)) { best = s; bi = j; }
        }
    }
    if (lane == 0) idxOut[row] = bi;
}

// ---------------- final combine ----------------
__global__ void final_kernel(float* __restrict__ out)
{
    const int r = blockIdx.x * blockDim.x + threadIdx.x;
    if (r >= MTOT) return;
    const float m0 = g_m[0][r], m1 = g_m[1][r];
    const int i0 = g_idx[0][r], i1 = g_idx[1][r];
    const bool c0 = (i0 != 0) && (m0 >= 0.1f);
    const bool c1 = c0 && (i1 != 0) && (m1 >= 0.1f);
    const float score = c0 ? (c1 ? m0 * m1 : m0) : 0.f;
    out[r]            = score;
    out[MTOT + r]     = (float)i0;
    out[2 * MTOT + r] = (float)i1;
    out[3 * MTOT + r] = (float)((int)c0 + (int)c1);
}

// ---------------- launch ----------------
extern "C" void kernel_launch(void* const* d_in, const int* in_sizes, int n_in,
                              void* d_out, int out_size)
{
    const float* x    = (const float*)d_in[0];
    const float* na   = (const float*)d_in[1];
    const float* v_w  = (const float*)d_in[2];
    const float* v_b  = (const float*)d_in[3];
    const float* o_w  = (const float*)d_in[4];
    const float* o_b  = (const float*)d_in[5];
    const float* ln_g = (const float*)d_in[6];
    const float* ln_b = (const float*)d_in[7];
    const float* w1   = (const float*)d_in[8];
    const float* b1   = (const float*)d_in[9];
    const float* w2   = (const float*)d_in[10];
    const float* b2   = (const float*)d_in[11];
    float* out = (float*)d_out;

    float *Wc, *bc, *attn, *gactf, *m, *scales;
    __nv_bfloat16 *xh, *xl, *Wch, *Wcl, *w1h, *w1l, *hh, *hl, *logits;
    int8_t *gact8, *w28;
    int *idx, *cnt, *cand;
    cudaGetSymbolAddress((void**)&Wc, g_Wc);
    cudaGetSymbolAddress((void**)&bc, g_bc);
    cudaGetSymbolAddress((void**)&xh, g_xh);
    cudaGetSymbolAddress((void**)&xl, g_xl);
    cudaGetSymbolAddress((void**)&Wch, g_Wch);
    cudaGetSymbolAddress((void**)&Wcl, g_Wcl);
    cudaGetSymbolAddress((void**)&w1h, g_w1h);
    cudaGetSymbolAddress((void**)&w1l, g_w1l);
    cudaGetSymbolAddress((void**)&attn, g_attn);
    cudaGetSymbolAddress((void**)&hh, g_hh);
    cudaGetSymbolAddress((void**)&hl, g_hl);
    cudaGetSymbolAddress((void**)&gactf, g_gactf);
    cudaGetSymbolAddress((void**)&gact8, g_gact8);
    cudaGetSymbolAddress((void**)&w28, g_w28);
    cudaGetSymbolAddress((void**)&logits, g_logits);
    cudaGetSymbolAddress((void**)&m, g_m);
    cudaGetSymbolAddress((void**)&idx, g_idx);
    cudaGetSymbolAddress((void**)&cnt, g_cnt);
    cudaGetSymbolAddress((void**)&cand, g_cand);
    cudaGetSymbolAddress((void**)&scales, g_scales);

    cudaFuncSetAttribute(mma_gemm<0>, cudaFuncAttributeMaxDynamicSharedMemorySize, GSMEM);
    cudaFuncSetAttribute(mma_gemm<1>, cudaFuncAttributeMaxDynamicSharedMemorySize, GSMEM);
    cudaFuncSetAttribute(mma_gemm_s8, cudaFuncAttributeMaxDynamicSharedMemorySize, GSMEM);

    // weight prep
    zero_scales_kernel<<<1, 32>>>();
    combine_w_kernel<<<dim3(32, 32), dim3(16, 16)>>>(o_w, v_w, Wc);
    combine_b_kernel<<<1, 512>>>(o_w, v_b, o_b, bc);
    split_kernel<<<(DMODEL * DMODEL / 4 + 255) / 256, 256>>>(Wc, Wch, Wcl, DMODEL * DMODEL / 4);
    split_kernel<<<(HID2 * DMODEL / 4 + 255) / 256, 256>>>(w1, w1h, w1l, HID2 * DMODEL / 4);
    split_kernel<<<(MTOT * DMODEL / 4 + 255) / 256, 256>>>(x, xh, xl, MTOT * DMODEL / 4);
    absmax_kernel<<<592, 256>>>(w2, NRELS * HID2, (int*)&scales[0]);
    quant_kernel<<<(NRELS * HID2 / 4 + 255) / 256, 256>>>(w2, w28, &scales[0], NRELS * HID2 / 4);

    // attn = x @ Wc^T + bc   (4-term split)
    mma_gemm<0><<<dim3(DMODEL / 128, MTOT / 128), 256, GSMEM>>>(
        xh, xh, xl, xl, Wch, Wcl, Wch, Wcl, bc, attn, nullptr,
        DMODEL, DMODEL, DMODEL / 64, 4 * DMODEL / 64);

    for (int s = 0; s < 2; s++) {
        const float* state = s ? x : na;
        const int sstride  = s ? DMODEL : 0;
        ln_kernel<<<MTOT / 8, 256>>>(attn, state, sstride, ln_g, ln_b, hh, hl);
        // gact = relu(h @ w1^T + b1)  (4-term split) -> fp32 + tensor max
        mma_gemm<1><<<dim3(HID2 / 128, MTOT / 128), 256, GSMEM>>>(
            hh, hh, hl, hl, w1h, w1l, w1h, w1l, b1, gactf, (int*)&scales[1 + s],
            HID2, DMODEL, DMODEL / 64, 4 * DMODEL / 64);
        quant_kernel<<<(MTOT * HID2 / 4 + 255) / 256, 256>>>(gactf, gact8, &scales[1 + s],
                                                             MTOT * HID2 / 4);
        // logits = (gact8 @ w28^T)*scale + b2   (int8 IMMA, k32)
        mma_gemm_s8<<<dim3(NRELS / 128, MTOT / 128), 256, GSMEM>>>(
            gact8, w28, b2, &scales[1 + s], &scales[0], logits,
            NRELS, HID2, HID2 / 128);
        reduce2_kernel<<<MTOT / 8, 256>>>(logits, m + s * MTOT, cnt, cand);
        rescue_kernel<<<MTOT / 8, 256>>>(gactf, w2, b2, cnt, cand, idx + s * MTOT);
    }

    final_kernel<<<MTOT / 256, 256>>>(out);
}

// round 11
// speedup vs baseline: 1.6940x; 1.6940x over previous
#include <cuda_runtime.h>
#include <cuda_bf16.h>
#include <cstdint>

#define MTOT   32768
#define DMODEL 512
#define HID2   1024
#define NRELS  2048
#define CAND   32
#define STAGE_B 32768                 // A 128x64 (16KB) + B 128x64 (16KB)
#define GSMEM  (3 * STAGE_B)          // 3 stages = 96KB -> 2 CTAs/SM

// ---------------- scratch (static device globals; no allocs) ----------------
__device__ float          g_Wc[DMODEL * DMODEL];
__device__ float          g_bc[DMODEL];
__device__ __nv_bfloat16  g_xh[MTOT * DMODEL],  g_xl[MTOT * DMODEL];
__device__ __nv_bfloat16  g_Wch[DMODEL * DMODEL], g_Wcl[DMODEL * DMODEL];
__device__ __nv_bfloat16  g_w1h[HID2 * DMODEL],  g_w1l[HID2 * DMODEL];
__device__ __nv_bfloat16  g_w2b[NRELS * HID2];
__device__ float          g_attn[MTOT * DMODEL];
__device__ __nv_bfloat16  g_hh[MTOT * DMODEL],  g_hl[MTOT * DMODEL];
__device__ float          g_gactf[MTOT * HID2];
__device__ __nv_bfloat16  g_gactb[MTOT * HID2];
__device__ __nv_bfloat16  g_logits[MTOT * NRELS];
__device__ float          g_m[2][MTOT];
__device__ int            g_idx[2][MTOT];
__device__ int            g_cnt[MTOT];
__device__ int            g_cand[MTOT * CAND];

// ---------------- PTX helpers (baseline ISA only) ----------------
__device__ __forceinline__ uint32_t smem_u32(const void* p) {
    uint32_t a;
    asm("{ .reg .u64 t; cvta.to.shared.u64 t, %1; cvt.u32.u64 %0, t; }" : "=r"(a) : "l"(p));
    return a;
}

#define CP_ASYNC16(sp, gp) \
    asm volatile("cp.async.cg.shared.global [%0], [%1], 16;\n" :: "r"(sp), "l"(gp) : "memory")
#define CP_COMMIT()   asm volatile("cp.async.commit_group;\n" ::: "memory")
#define CP_WAIT1()    asm volatile("cp.async.wait_group 1;\n" ::: "memory")

#define LDSM_X4(r, addr) \
    asm volatile("ldmatrix.sync.aligned.m8n8.x4.shared.b16 {%0,%1,%2,%3}, [%4];" \
        : "=r"((r)[0]), "=r"((r)[1]), "=r"((r)[2]), "=r"((r)[3]) : "r"(addr))

__device__ __forceinline__ void mma16816(float* c, const uint32_t* a, uint32_t b0, uint32_t b1) {
    asm volatile(
        "mma.sync.aligned.m16n8k16.row.col.f32.bf16.bf16.f32 "
        "{%0,%1,%2,%3},{%4,%5,%6,%7},{%8,%9},{%0,%1,%2,%3};\n"
        : "+f"(c[0]), "+f"(c[1]), "+f"(c[2]), "+f"(c[3])
        : "r"(a[0]), "r"(a[1]), "r"(a[2]), "r"(a[3]), "r"(b0), "r"(b1));
}

// ldmatrix address into a (rows x 64 bf16) tile (128B rows, xor-swizzled 16B chunks)
__device__ __forceinline__ uint32_t ldsm_addr(uint32_t base, int row0, int chunk0, int lane) {
    const int r = row0 + (lane & 15);
    const int c = chunk0 + (lane >> 4);
    return base + r * 128 + ((c ^ (r & 7)) << 4);
}

// ---------------- bf16 HMMA GEMM: C[M,N] = sum_reg A_reg @ B_reg^T (+bias) ---
// CTA 128x128, 8 warps (2x4), warp tile 64x32, K-tile 64, 3-stage depth-2 cp.async.
// EPI 0: Cf fp32      EPI 1: relu -> Cf fp32 AND Cb bf16      EPI 2: Cb bf16
template <int EPI>
__global__ __launch_bounds__(256, 2) void mma_gemm(
    const __nv_bfloat16* __restrict__ A0, const __nv_bfloat16* __restrict__ A1,
    const __nv_bfloat16* __restrict__ A2, const __nv_bfloat16* __restrict__ A3,
    const __nv_bfloat16* __restrict__ B0, const __nv_bfloat16* __restrict__ B1,
    const __nv_bfloat16* __restrict__ B2, const __nv_bfloat16* __restrict__ B3,
    const float* __restrict__ bias, float* __restrict__ Cf, __nv_bfloat16* __restrict__ Cb,
    int N, int Kreg, int kcpr, int nch)
{
    extern __shared__ __align__(1024) char sm[];
    const int tid  = threadIdx.x;
    const int wid  = tid >> 5;
    const int lane = tid & 31;
    const int bm   = blockIdx.y * 128;
    const int bn   = blockIdx.x * 128;
    const int wm   = (wid >> 2) * 64;     // warp M offset
    const int wn   = (wid & 3) * 32;      // warp N offset

    const uint32_t sBase = smem_u32(sm);

    float acc[4][4][4];
#pragma unroll
    for (int i = 0; i < 4; i++)
#pragma unroll
        for (int j = 0; j < 4; j++)
#pragma unroll
            for (int k = 0; k < 4; k++) acc[i][j][k] = 0.f;

    // ---- async tile loader: chunk c -> stage ----
    auto load_tile = [&](int c, int stage) {
        const int reg = c / kcpr;
        const int kc  = c - reg * kcpr;
        const __nv_bfloat16* Ar = (reg == 0) ? A0 : (reg == 1) ? A1 : (reg == 2) ? A2 : A3;
        const __nv_bfloat16* Br = (reg == 0) ? B0 : (reg == 1) ? B1 : (reg == 2) ? B2 : B3;
        const uint32_t aBase = sBase + stage * STAGE_B;
        const uint32_t bBase = aBase + 16384;
#pragma unroll
        for (int i = 0; i < 4; i++) {
            const int u = tid + 256 * i;           // 0..1023 (128 rows x 8 chunks)
            const int r = u >> 3, ch = u & 7;
            const uint32_t soff = r * 128 + ((ch ^ (r & 7)) << 4);
            CP_ASYNC16(aBase + soff, Ar + (size_t)(bm + r) * Kreg + kc * 64 + ch * 8);
            CP_ASYNC16(bBase + soff, Br + (size_t)(bn + r) * Kreg + kc * 64 + ch * 8);
        }
    };

    // prologue: stages 0,1
    load_tile(0, 0); CP_COMMIT();
    load_tile(1, 1); CP_COMMIT();

    int stage = 0;
    for (int c = 0; c < nch; c++) {
        CP_WAIT1();            // chunk c landed (c+1 still in flight)
        __syncthreads();       // all warps done reading stage being overwritten

        if (c + 2 < nch) load_tile(c + 2, (c + 2) % 3);
        CP_COMMIT();           // always commit to keep group numbering

        const uint32_t aB = sBase + stage * STAGE_B;
        const uint32_t bB = aB + 16384;
#pragma unroll
        for (int kk = 0; kk < 4; kk++) {
            uint32_t ar[4][4], br[2][4];
#pragma unroll
            for (int mt = 0; mt < 4; mt++)
                LDSM_X4(ar[mt], ldsm_addr(aB, wm + mt * 16, 2 * kk, lane));
#pragma unroll
            for (int nt = 0; nt < 2; nt++)
                LDSM_X4(br[nt], ldsm_addr(bB, wn + nt * 16, 2 * kk, lane));
#pragma unroll
            for (int mt = 0; mt < 4; mt++)
#pragma unroll
                for (int j = 0; j < 4; j++)
                    mma16816(acc[mt][j], ar[mt], br[j >> 1][j & 1], br[j >> 1][(j & 1) + 2]);
        }
        stage = (stage + 1) == 3 ? 0 : (stage + 1);
    }

    // ---- epilogue ----
    const int rbase = bm + wm + (lane >> 2);
    const int cbase = bn + wn + ((lane & 3) << 1);
#pragma unroll
    for (int mt = 0; mt < 4; mt++) {
#pragma unroll
        for (int j = 0; j < 4; j++) {
            const int row = rbase + mt * 16;
            const int col = cbase + j * 8;
            const float b0 = __ldg(&bias[col]), b1 = __ldg(&bias[col + 1]);
            float v0 = acc[mt][j][0] + b0, v1 = acc[mt][j][1] + b1;
            float v2 = acc[mt][j][2] + b0, v3 = acc[mt][j][3] + b1;
            if (EPI == 1) {
                v0 = fmaxf(v0, 0.f); v1 = fmaxf(v1, 0.f);
                v2 = fmaxf(v2, 0.f); v3 = fmaxf(v3, 0.f);
            }
            if (EPI == 0 || EPI == 1) {
                *(float2*)(Cf + (size_t)row * N + col)       = make_float2(v0, v1);
                *(float2*)(Cf + (size_t)(row + 8) * N + col) = make_float2(v2, v3);
            }
            if (EPI == 1 || EPI == 2) {
                __nv_bfloat162 p0 = __floats2bfloat162_rn(v0, v1);
                __nv_bfloat162 p1 = __floats2bfloat162_rn(v2, v3);
                *(__nv_bfloat162*)(Cb + (size_t)row * N + col)       = p0;
                *(__nv_bfloat162*)(Cb + (size_t)(row + 8) * N + col) = p1;
            }
        }
    }
}

// ---------------- small prep kernels ----------------
__global__ void combine_w_kernel(const float* __restrict__ ow, const float* __restrict__ vw,
                                 float* __restrict__ wc)
{
    __shared__ float As[16][16];
    __shared__ float Bs[16][17];
    const int tx = threadIdx.x, ty = threadIdx.y;
    const int i = blockIdx.y * 16 + ty;
    const int j = blockIdx.x * 16 + tx;
    float acc = 0.f;
    for (int k0 = 0; k0 < DMODEL; k0 += 16) {
        As[ty][tx] = ow[i * DMODEL + k0 + tx];
        Bs[ty][tx] = vw[(k0 + ty) * DMODEL + j];
        __syncthreads();
#pragma unroll
        for (int kk = 0; kk < 16; kk++) acc = fmaf(As[ty][kk], Bs[kk][tx], acc);
        __syncthreads();
    }
    wc[i * DMODEL + j] = acc;
}

__global__ void combine_b_kernel(const float* __restrict__ ow, const float* __restrict__ vb,
                                 const float* __restrict__ ob, float* __restrict__ bc)
{
    const int i = threadIdx.x;
    float acc = 0.f;
    for (int k = 0; k < DMODEL; k++) acc = fmaf(ow[i * DMODEL + k], vb[k], acc);
    bc[i] = acc + ob[i];
}

// fp32 -> (bf16 hi, bf16 lo) split, 4 elems / thread
__global__ void split_kernel(const float* __restrict__ in, __nv_bfloat16* __restrict__ hi,
                             __nv_bfloat16* __restrict__ lo, int n4)
{
    const int i = blockIdx.x * blockDim.x + threadIdx.x;
    if (i >= n4) return;
    float4 v = ((const float4*)in)[i];
    __nv_bfloat16 h0 = __float2bfloat16_rn(v.x), h1 = __float2bfloat16_rn(v.y);
    __nv_bfloat16 h2 = __float2bfloat16_rn(v.z), h3 = __float2bfloat16_rn(v.w);
    __nv_bfloat16 l0 = __float2bfloat16_rn(v.x - __bfloat162float(h0));
    __nv_bfloat16 l1 = __float2bfloat16_rn(v.y - __bfloat162float(h1));
    __nv_bfloat16 l2 = __float2bfloat16_rn(v.z - __bfloat162float(h2));
    __nv_bfloat16 l3 = __float2bfloat16_rn(v.w - __bfloat162float(h3));
    __nv_bfloat162* H = (__nv_bfloat162*)hi;
    __nv_bfloat162* L = (__nv_bfloat162*)lo;
    H[2 * i] = __nv_bfloat162(h0, h1); H[2 * i + 1] = __nv_bfloat162(h2, h3);
    L[2 * i] = __nv_bfloat162(l0, l1); L[2 * i + 1] = __nv_bfloat162(l2, l3);
}

__global__ void round_kernel(const float* __restrict__ in, __nv_bfloat16* __restrict__ out, int n4)
{
    const int i = blockIdx.x * blockDim.x + threadIdx.x;
    if (i >= n4) return;
    float4 v = ((const float4*)in)[i];
    __nv_bfloat162* O = (__nv_bfloat162*)out;
    O[2 * i]     = __floats2bfloat162_rn(v.x, v.y);
    O[2 * i + 1] = __floats2bfloat162_rn(v.z, v.w);
}

// ---------------- LayerNorm(attn + state) -> split bf16 planes --------------
__global__ __launch_bounds__(256) void ln_kernel(
    const float* __restrict__ attn, const float* __restrict__ state, int sstride,
    const float* __restrict__ gamma, const float* __restrict__ beta,
    __nv_bfloat16* __restrict__ hh, __nv_bfloat16* __restrict__ hl)
{
    const int warp = threadIdx.x >> 5, lane = threadIdx.x & 31;
    const int row = blockIdx.x * 8 + warp;
    const float4* ap = (const float4*)(attn + (size_t)row * DMODEL);
    const float4* sp = (const float4*)(state + (size_t)row * sstride);

    float v[16];
    float s = 0.f, ss = 0.f;
#pragma unroll
    for (int q = 0; q < 4; q++) {
        float4 a = ap[lane + 32 * q];
        float4 st = sp[lane + 32 * q];
        float x0 = a.x + st.x, x1 = a.y + st.y, x2 = a.z + st.z, x3 = a.w + st.w;
        v[4 * q] = x0; v[4 * q + 1] = x1; v[4 * q + 2] = x2; v[4 * q + 3] = x3;
        s += x0 + x1 + x2 + x3;
        ss += x0 * x0 + x1 * x1 + x2 * x2 + x3 * x3;
    }
#pragma unroll
    for (int o = 16; o; o >>= 1) {
        s  += __shfl_xor_sync(0xffffffffu, s, o);
        ss += __shfl_xor_sync(0xffffffffu, ss, o);
    }
    const float mean = s * (1.f / DMODEL);
    const float var  = ss * (1.f / DMODEL) - mean * mean;
    const float inv  = rsqrtf(var + 1e-5f);

    const float4* gp = (const float4*)gamma;
    const float4* bp = (const float4*)beta;
    uint2* hp = (uint2*)(hh + (size_t)row * DMODEL);
    uint2* lp = (uint2*)(hl + (size_t)row * DMODEL);
#pragma unroll
    for (int q = 0; q < 4; q++) {
        float4 g = gp[lane + 32 * q], b = bp[lane + 32 * q];
        float o0 = (v[4 * q] - mean) * inv * g.x + b.x;
        float o1 = (v[4 * q + 1] - mean) * inv * g.y + b.y;
        float o2 = (v[4 * q + 2] - mean) * inv * g.z + b.z;
        float o3 = (v[4 * q + 3] - mean) * inv * g.w + b.w;
        __nv_bfloat16 h0 = __float2bfloat16_rn(o0), h1 = __float2bfloat16_rn(o1);
        __nv_bfloat16 h2 = __float2bfloat16_rn(o2), h3 = __float2bfloat16_rn(o3);
        __nv_bfloat162 ph0(h0, h1), ph1(h2, h3);
        __nv_bfloat162 pl0(__float2bfloat16_rn(o0 - __bfloat162float(h0)),
                           __float2bfloat16_rn(o1 - __bfloat162float(h1)));
        __nv_bfloat162 pl1(__float2bfloat16_rn(o2 - __bfloat162float(h2)),
                           __float2bfloat16_rn(o3 - __bfloat162float(h3)));
        hp[lane + 32 * q] = make_uint2(*(uint32_t*)&ph0, *(uint32_t*)&ph1);
        lp[lane + 32 * q] = make_uint2(*(uint32_t*)&pl0, *(uint32_t*)&pl1);
    }
}

// --------- per-row: max / 1/sumexp / candidate set from bf16 logits ---------
__device__ __forceinline__ float2 bf2f2(uint32_t w) {
    float2 r;
    r.x = __uint_as_float(w << 16);
    r.y = __uint_as_float(w & 0xffff0000u);
    return r;
}

__global__ __launch_bounds__(256) void reduce2_kernel(
    const __nv_bfloat16* __restrict__ logits, float* __restrict__ mOut,
    int* __restrict__ cnt, int* __restrict__ cand)
{
    __shared__ int scnt[8];
    const int warp = threadIdx.x >> 5, lane = threadIdx.x & 31;
    const int row = blockIdx.x * 8 + warp;
    const uint4* lp = (const uint4*)(logits + (size_t)row * NRELS);

    float vmax = -3.4e38f;
#pragma unroll
    for (int q = 0; q < 8; q++) {
        uint4 u = lp[lane + 32 * q];
        float2 a = bf2f2(u.x), b = bf2f2(u.y), c = bf2f2(u.z), d = bf2f2(u.w);
        vmax = fmaxf(vmax, fmaxf(fmaxf(fmaxf(a.x, a.y), fmaxf(b.x, b.y)),
                                 fmaxf(fmaxf(c.x, c.y), fmaxf(d.x, d.y))));
    }
#pragma unroll
    for (int o = 16; o; o >>= 1) vmax = fmaxf(vmax, __shfl_xor_sync(0xffffffffu, vmax, o));

    if (lane == 0) scnt[warp] = 0;
    __syncwarp();

    const float thr = vmax - 0.02f;
    float se = 0.f;
#pragma unroll
    for (int q = 0; q < 8; q++) {
        uint4 u = lp[lane + 32 * q];
        uint32_t ws[4] = {u.x, u.y, u.z, u.w};
        const int base = (lane + 32 * q) * 8;
#pragma unroll
        for (int wI = 0; wI < 4; wI++) {
            float2 e = bf2f2(ws[wI]);
            se += __expf(e.x - vmax) + __expf(e.y - vmax);
            if (e.x >= thr) {
                int p = atomicAdd(&scnt[warp], 1);
                if (p < CAND) cand[(size_t)row * CAND + p] = base + 2 * wI;
            }
            if (e.y >= thr) {
                int p = atomicAdd(&scnt[warp], 1);
                if (p < CAND) cand[(size_t)row * CAND + p] = base + 2 * wI + 1;
            }
        }
    }
#pragma unroll
    for (int o = 16; o; o >>= 1) se += __shfl_xor_sync(0xffffffffu, se, o);
    __syncwarp();
    if (lane == 0) { mOut[row] = 1.f / se; cnt[row] = scnt[warp]; }
}

// --------- exact fp32 rescue of the argmax among candidates ---------
__global__ __launch_bounds__(256) void rescue_kernel(
    const float* __restrict__ gact, const float* __restrict__ w2,
    const float* __restrict__ b2, const int* __restrict__ cnt,
    const int* __restrict__ cand, int* __restrict__ idxOut)
{
    const int warp = threadIdx.x >> 5, lane = threadIdx.x & 31;
    const int row = blockIdx.x * 8 + warp;
    const float* g = gact + (size_t)row * HID2;
    const int n = cnt[row];

    float best = -3.4e38f;
    int bi = 0x7fffffff;
    if (n <= CAND) {
        for (int t = 0; t < n; t++) {
            const int j = cand[(size_t)row * CAND + t];
            const float* wr = w2 + (size_t)j * HID2;
            float s = 0.f;
            for (int k = lane; k < HID2; k += 32) s = fmaf(wr[k], g[k], s);
#pragma unroll
            for (int o = 16; o; o >>= 1) s += __shfl_xor_sync(0xffffffffu, s, o);
            s += b2[j];
            if (s > best || (s == best && j < bi)) { best = s; bi = j; }
        }
    } else {
        for (int j = 0; j < NRELS; j++) {
            const float* wr = w2 + (size_t)j * HID2;
            float s = 0.f;
            for (int k = lane; k < HID2; k += 32) s = fmaf(wr[k], g[k], s);
#pragma unroll
            for (int o = 16; o; o >>= 1) s += __shfl_xor_sync(0xffffffffu, s, o);
            s += b2[j];
            if (s > best || (s == best && j < bi)) { best = s; bi = j; }
        }
    }
    if (lane == 0) idxOut[row] = bi;
}

// ---------------- final combine ----------------
__global__ void final_kernel(float* __restrict__ out)
{
    const int r = blockIdx.x * blockDim.x + threadIdx.x;
    if (r >= MTOT) return;
    const float m0 = g_m[0][r], m1 = g_m[1][r];
    const int i0 = g_idx[0][r], i1 = g_idx[1][r];
    const bool c0 = (i0 != 0) && (m0 >= 0.1f);
    const bool c1 = c0 && (i1 != 0) && (m1 >= 0.1f);
    const float score = c0 ? (c1 ? m0 * m1 : m0) : 0.f;
    out[r]            = score;
    out[MTOT + r]     = (float)i0;
    out[2 * MTOT + r] = (float)i1;
    out[3 * MTOT + r] = (float)((int)c0 + (int)c1);
}

// ---------------- launch ----------------
extern "C" void kernel_launch(void* const* d_in, const int* in_sizes, int n_in,
                              void* d_out, int out_size)
{
    const float* x    = (const float*)d_in[0];
    const float* na   = (const float*)d_in[1];
    const float* v_w  = (const float*)d_in[2];
    const float* v_b  = (const float*)d_in[3];
    const float* o_w  = (const float*)d_in[4];
    const float* o_b  = (const float*)d_in[5];
    const float* ln_g = (const float*)d_in[6];
    const float* ln_b = (const float*)d_in[7];
    const float* w1   = (const float*)d_in[8];
    const float* b1   = (const float*)d_in[9];
    const float* w2   = (const float*)d_in[10];
    const float* b2   = (const float*)d_in[11];
    float* out = (float*)d_out;

    float *Wc, *bc, *attn, *gactf, *m;
    __nv_bfloat16 *xh, *xl, *Wch, *Wcl, *w1h, *w1l, *w2b, *hh, *hl, *gactb, *logits;
    int *idx, *cnt, *cand;
    cudaGetSymbolAddress((void**)&Wc, g_Wc);
    cudaGetSymbolAddress((void**)&bc, g_bc);
    cudaGetSymbolAddress((void**)&xh, g_xh);
    cudaGetSymbolAddress((void**)&xl, g_xl);
    cudaGetSymbolAddress((void**)&Wch, g_Wch);
    cudaGetSymbolAddress((void**)&Wcl, g_Wcl);
    cudaGetSymbolAddress((void**)&w1h, g_w1h);
    cudaGetSymbolAddress((void**)&w1l, g_w1l);
    cudaGetSymbolAddress((void**)&w2b, g_w2b);
    cudaGetSymbolAddress((void**)&attn, g_attn);
    cudaGetSymbolAddress((void**)&hh, g_hh);
    cudaGetSymbolAddress((void**)&hl, g_hl);
    cudaGetSymbolAddress((void**)&gactf, g_gactf);
    cudaGetSymbolAddress((void**)&gactb, g_gactb);
    cudaGetSymbolAddress((void**)&logits, g_logits);
    cudaGetSymbolAddress((void**)&m, g_m);
    cudaGetSymbolAddress((void**)&idx, g_idx);
    cudaGetSymbolAddress((void**)&cnt, g_cnt);
    cudaGetSymbolAddress((void**)&cand, g_cand);

    cudaFuncSetAttribute(mma_gemm<0>, cudaFuncAttributeMaxDynamicSharedMemorySize, GSMEM);
    cudaFuncSetAttribute(mma_gemm<1>, cudaFuncAttributeMaxDynamicSharedMemorySize, GSMEM);
    cudaFuncSetAttribute(mma_gemm<2>, cudaFuncAttributeMaxDynamicSharedMemorySize, GSMEM);

    // weight prep
    combine_w_kernel<<<dim3(32, 32), dim3(16, 16)>>>(o_w, v_w, Wc);
    combine_b_kernel<<<1, 512>>>(o_w, v_b, o_b, bc);
    split_kernel<<<(DMODEL * DMODEL / 4 + 255) / 256, 256>>>(Wc, Wch, Wcl, DMODEL * DMODEL / 4);
    split_kernel<<<(HID2 * DMODEL / 4 + 255) / 256, 256>>>(w1, w1h, w1l, HID2 * DMODEL / 4);
    round_kernel<<<(NRELS * HID2 / 4 + 255) / 256, 256>>>(w2, w2b, NRELS * HID2 / 4);
    split_kernel<<<(MTOT * DMODEL / 4 + 255) / 256, 256>>>(x, xh, xl, MTOT * DMODEL / 4);

    // attn = x @ Wc^T + bc   (3-term split: xh*wh + xh*wl + xl*wh)
    mma_gemm<0><<<dim3(DMODEL / 128, MTOT / 128), 256, GSMEM>>>(
        xh, xh, xl, xl, Wch, Wcl, Wch, Wcl, bc, attn, nullptr,
        DMODEL, DMODEL, DMODEL / 64, 3 * DMODEL / 64);

    for (int s = 0; s < 2; s++) {
        const float* state = s ? x : na;
        const int sstride  = s ? DMODEL : 0;
        ln_kernel<<<MTOT / 8, 256>>>(attn, state, sstride, ln_g, ln_b, hh, hl);
        // gact = relu(h @ w1^T + b1)  (3-term split) -> fp32 + bf16
        mma_gemm<1><<<dim3(HID2 / 128, MTOT / 128), 256, GSMEM>>>(
            hh, hh, hl, hl, w1h, w1l, w1h, w1l, b1, gactf, gactb,
            HID2, DMODEL, DMODEL / 64, 3 * DMODEL / 64);
        // logits = gact @ w2^T + b2  (1-pass bf16)
        mma_gemm<2><<<dim3(NRELS / 128, MTOT / 128), 256, GSMEM>>>(
            gactb, gactb, gactb, gactb, w2b, w2b, w2b, w2b, b2, nullptr, logits,
            NRELS, HID2, HID2 / 64, HID2 / 64);
        reduce2_kernel<<<MTOT / 8, 256>>>(logits, m + s * MTOT, cnt, cand);
        rescue_kernel<<<MTOT / 8, 256>>>(gactf, w2, b2, cnt, cand, idx + s * MTOT);
    }

    final_kernel<<<MTOT / 256, 256>>>(out);
}

// round 13
// speedup vs baseline: 1.6943x; 1.0002x over previous
#include <cuda_runtime.h>
#include <cuda_bf16.h>
#include <cstdint>

#define MTOT   32768
#define MB2    (2 * MTOT)
#define DMODEL 512
#define HID2   1024
#define NRELS  2048
#define CAND   32
#define STAGE_B 32768                 // A 128x64 (16KB) + B 128x64 (16KB)
#define GSMEM  (3 * STAGE_B)          // 3 stages = 96KB -> 2 CTAs/SM

// ---------------- scratch (static device globals; no allocs) ----------------
__device__ float          g_Wc[DMODEL * DMODEL];
__device__ float          g_bc[DMODEL];
__device__ __nv_bfloat16  g_xh[MTOT * DMODEL],  g_xl[MTOT * DMODEL];
__device__ __nv_bfloat16  g_Wch[DMODEL * DMODEL], g_Wcl[DMODEL * DMODEL];
__device__ __nv_bfloat16  g_w1h[HID2 * DMODEL],  g_w1l[HID2 * DMODEL];
__device__ __nv_bfloat16  g_w2b[NRELS * HID2];
__device__ float          g_attn[MTOT * DMODEL];
__device__ __nv_bfloat16  g_hh[MB2 * DMODEL],  g_hl[MB2 * DMODEL];
__device__ float          g_gactf[MB2 * HID2];
__device__ __nv_bfloat16  g_gactb[MB2 * HID2];
__device__ __nv_bfloat16  g_logits[MB2 * NRELS];
__device__ float          g_m[MB2];
__device__ int            g_idx[MB2];
__device__ int            g_cnt[MB2];
__device__ int            g_cand[MB2 * CAND];

// ---------------- PTX helpers (baseline ISA only) ----------------
__device__ __forceinline__ uint32_t smem_u32(const void* p) {
    uint32_t a;
    asm("{ .reg .u64 t; cvta.to.shared.u64 t, %1; cvt.u32.u64 %0, t; }" : "=r"(a) : "l"(p));
    return a;
}

#define CP_ASYNC16(sp, gp) \
    asm volatile("cp.async.cg.shared.global [%0], [%1], 16;\n" :: "r"(sp), "l"(gp) : "memory")
#define CP_COMMIT()   asm volatile("cp.async.commit_group;\n" ::: "memory")
#define CP_WAIT1()    asm volatile("cp.async.wait_group 1;\n" ::: "memory")

#define LDSM_X4(r, addr) \
    asm volatile("ldmatrix.sync.aligned.m8n8.x4.shared.b16 {%0,%1,%2,%3}, [%4];" \
        : "=r"((r)[0]), "=r"((r)[1]), "=r"((r)[2]), "=r"((r)[3]) : "r"(addr))

__device__ __forceinline__ void mma16816(float* c, const uint32_t* a, uint32_t b0, uint32_t b1) {
    asm volatile(
        "mma.sync.aligned.m16n8k16.row.col.f32.bf16.bf16.f32 "
        "{%0,%1,%2,%3},{%4,%5,%6,%7},{%8,%9},{%0,%1,%2,%3};\n"
        : "+f"(c[0]), "+f"(c[1]), "+f"(c[2]), "+f"(c[3])
        : "r"(a[0]), "r"(a[1]), "r"(a[2]), "r"(a[3]), "r"(b0), "r"(b1));
}

// ldmatrix address into a (rows x 64 bf16) tile (128B rows, xor-swizzled 16B chunks)
__device__ __forceinline__ uint32_t ldsm_addr(uint32_t base, int row0, int chunk0, int lane) {
    const int r = row0 + (lane & 15);
    const int c = chunk0 + (lane >> 4);
    return base + r * 128 + ((c ^ (r & 7)) << 4);
}

// ---------------- bf16 HMMA GEMM (persistent tiles) --------------------------
// C[M,N] = sum_reg A_reg @ B_reg^T (+bias). CTA 128x128, 8 warps, warp 64x32,
// K-tile 64, 3-stage depth-2 cp.async, grid-stride over tiles.
// EPI 0: Cf fp32      EPI 1: relu -> Cf fp32 AND Cb bf16      EPI 2: Cb bf16
template <int EPI>
__global__ __launch_bounds__(256, 2) void mma_gemm(
    const __nv_bfloat16* __restrict__ A0, const __nv_bfloat16* __restrict__ A1,
    const __nv_bfloat16* __restrict__ A2, const __nv_bfloat16* __restrict__ A3,
    const __nv_bfloat16* __restrict__ B0, const __nv_bfloat16* __restrict__ B1,
    const __nv_bfloat16* __restrict__ B2, const __nv_bfloat16* __restrict__ B3,
    const float* __restrict__ bias, float* __restrict__ Cf, __nv_bfloat16* __restrict__ Cb,
    int N, int Kreg, int kcpr, int nch, int ntx, int ntiles)
{
    extern __shared__ __align__(1024) char sm[];
    const int tid  = threadIdx.x;
    const int wid  = tid >> 5;
    const int lane = tid & 31;
    const int wm   = (wid >> 2) * 64;
    const int wn   = (wid & 3) * 32;
    const uint32_t sBase = smem_u32(sm);

    for (int t = blockIdx.x; t < ntiles; t += gridDim.x) {
        const int bm = (t / ntx) * 128;
        const int bn = (t % ntx) * 128;

        float acc[4][4][4];
#pragma unroll
        for (int i = 0; i < 4; i++)
#pragma unroll
            for (int j = 0; j < 4; j++)
#pragma unroll
                for (int k = 0; k < 4; k++) acc[i][j][k] = 0.f;

        auto load_tile = [&](int c, int stage) {
            const int reg = c / kcpr;
            const int kc  = c - reg * kcpr;
            const __nv_bfloat16* Ar = (reg == 0) ? A0 : (reg == 1) ? A1 : (reg == 2) ? A2 : A3;
            const __nv_bfloat16* Br = (reg == 0) ? B0 : (reg == 1) ? B1 : (reg == 2) ? B2 : B3;
            const uint32_t aBase = sBase + stage * STAGE_B;
            const uint32_t bBase = aBase + 16384;
#pragma unroll
            for (int i = 0; i < 4; i++) {
                const int u = tid + 256 * i;           // 0..1023 (128 rows x 8 chunks)
                const int r = u >> 3, ch = u & 7;
                const uint32_t soff = r * 128 + ((ch ^ (r & 7)) << 4);
                CP_ASYNC16(aBase + soff, Ar + (size_t)(bm + r) * Kreg + kc * 64 + ch * 8);
                CP_ASYNC16(bBase + soff, Br + (size_t)(bn + r) * Kreg + kc * 64 + ch * 8);
            }
        };

        __syncthreads();                 // all warps done with prev tile's smem
        load_tile(0, 0); CP_COMMIT();
        load_tile(1, 1); CP_COMMIT();

        int stage = 0;
        for (int c = 0; c < nch; c++) {
            CP_WAIT1();
            __syncthreads();
            if (c + 2 < nch) load_tile(c + 2, (c + 2) % 3);
            CP_COMMIT();

            const uint32_t aB = sBase + stage * STAGE_B;
            const uint32_t bB = aB + 16384;
#pragma unroll
            for (int kk = 0; kk < 4; kk++) {
                uint32_t ar[4][4], br[2][4];
#pragma unroll
                for (int mt = 0; mt < 4; mt++)
                    LDSM_X4(ar[mt], ldsm_addr(aB, wm + mt * 16, 2 * kk, lane));
#pragma unroll
                for (int nt = 0; nt < 2; nt++)
                    LDSM_X4(br[nt], ldsm_addr(bB, wn + nt * 16, 2 * kk, lane));
#pragma unroll
                for (int mt = 0; mt < 4; mt++)
#pragma unroll
                    for (int j = 0; j < 4; j++)
                        mma16816(acc[mt][j], ar[mt], br[j >> 1][j & 1], br[j >> 1][(j & 1) + 2]);
            }
            stage = (stage + 1) == 3 ? 0 : (stage + 1);
        }

        // ---- epilogue ----
        const int rbase = bm + wm + (lane >> 2);
        const int cbase = bn + wn + ((lane & 3) << 1);
#pragma unroll
        for (int mt = 0; mt < 4; mt++) {
#pragma unroll
            for (int j = 0; j < 4; j++) {
                const int row = rbase + mt * 16;
                const int col = cbase + j * 8;
                const float b0 = __ldg(&bias[col]), b1 = __ldg(&bias[col + 1]);
                float v0 = acc[mt][j][0] + b0, v1 = acc[mt][j][1] + b1;
                float v2 = acc[mt][j][2] + b0, v3 = acc[mt][j][3] + b1;
                if (EPI == 1) {
                    v0 = fmaxf(v0, 0.f); v1 = fmaxf(v1, 0.f);
                    v2 = fmaxf(v2, 0.f); v3 = fmaxf(v3, 0.f);
                }
                if (EPI == 0 || EPI == 1) {
                    *(float2*)(Cf + (size_t)row * N + col)       = make_float2(v0, v1);
                    *(float2*)(Cf + (size_t)(row + 8) * N + col) = make_float2(v2, v3);
                }
                if (EPI == 1 || EPI == 2) {
                    __nv_bfloat162 p0 = __floats2bfloat162_rn(v0, v1);
                    __nv_bfloat162 p1 = __floats2bfloat162_rn(v2, v3);
                    *(__nv_bfloat162*)(Cb + (size_t)row * N + col)       = p0;
                    *(__nv_bfloat162*)(Cb + (size_t)(row + 8) * N + col) = p1;
                }
            }
        }
    }
}

// ---------------- small prep kernels ----------------
__global__ void combine_w_kernel(const float* __restrict__ ow, const float* __restrict__ vw,
                                 float* __restrict__ wc)
{
    __shared__ float As[16][16];
    __shared__ float Bs[16][17];
    const int tx = threadIdx.x, ty = threadIdx.y;
    const int i = blockIdx.y * 16 + ty;
    const int j = blockIdx.x * 16 + tx;
    float acc = 0.f;
    for (int k0 = 0; k0 < DMODEL; k0 += 16) {
        As[ty][tx] = ow[i * DMODEL + k0 + tx];
        Bs[ty][tx] = vw[(k0 + ty) * DMODEL + j];
        __syncthreads();
#pragma unroll
        for (int kk = 0; kk < 16; kk++) acc = fmaf(As[ty][kk], Bs[kk][tx], acc);
        __syncthreads();
    }
    wc[i * DMODEL + j] = acc;
}

__global__ void combine_b_kernel(const float* __restrict__ ow, const float* __restrict__ vb,
                                 const float* __restrict__ ob, float* __restrict__ bc)
{
    const int i = threadIdx.x;
    float acc = 0.f;
    for (int k = 0; k < DMODEL; k++) acc = fmaf(ow[i * DMODEL + k], vb[k], acc);
    bc[i] = acc + ob[i];
}

// fp32 -> (bf16 hi, bf16 lo) split, 4 elems / thread
__global__ void split_kernel(const float* __restrict__ in, __nv_bfloat16* __restrict__ hi,
                             __nv_bfloat16* __restrict__ lo, int n4)
{
    const int i = blockIdx.x * blockDim.x + threadIdx.x;
    if (i >= n4) return;
    float4 v = ((const float4*)in)[i];
    __nv_bfloat16 h0 = __float2bfloat16_rn(v.x), h1 = __float2bfloat16_rn(v.y);
    __nv_bfloat16 h2 = __float2bfloat16_rn(v.z), h3 = __float2bfloat16_rn(v.w);
    __nv_bfloat16 l0 = __float2bfloat16_rn(v.x - __bfloat162float(h0));
    __nv_bfloat16 l1 = __float2bfloat16_rn(v.y - __bfloat162float(h1));
    __nv_bfloat16 l2 = __float2bfloat16_rn(v.z - __bfloat162float(h2));
    __nv_bfloat16 l3 = __float2bfloat16_rn(v.w - __bfloat162float(h3));
    __nv_bfloat162* H = (__nv_bfloat162*)hi;
    __nv_bfloat162* L = (__nv_bfloat162*)lo;
    H[2 * i] = __nv_bfloat162(h0, h1); H[2 * i + 1] = __nv_bfloat162(h2, h3);
    L[2 * i] = __nv_bfloat162(l0, l1); L[2 * i + 1] = __nv_bfloat162(l2, l3);
}

__global__ void round_kernel(const float* __restrict__ in, __nv_bfloat16* __restrict__ out, int n4)
{
    const int i = blockIdx.x * blockDim.x + threadIdx.x;
    if (i >= n4) return;
    float4 v = ((const float4*)in)[i];
    __nv_bfloat162* O = (__nv_bfloat162*)out;
    O[2 * i]     = __floats2bfloat162_rn(v.x, v.y);
    O[2 * i + 1] = __floats2bfloat162_rn(v.z, v.w);
}

// ------- LayerNorm(attn + state) -> split bf16 planes, BOTH steps batched ----
// rows [0, MTOT): state = na (broadcast).  rows [MTOT, 2*MTOT): state = x row.
__global__ __launch_bounds__(256) void ln_kernel(
    const float* __restrict__ attn, const float* __restrict__ na, const float* __restrict__ x,
    const float* __restrict__ gamma, const float* __restrict__ beta,
    __nv_bfloat16* __restrict__ hh, __nv_bfloat16* __restrict__ hl)
{
    const int warp = threadIdx.x >> 5, lane = threadIdx.x & 31;
    const int u = blockIdx.x * 8 + warp;
    const int r = (u < MTOT) ? u : (u - MTOT);
    const float4* ap = (const float4*)(attn + (size_t)r * DMODEL);
    const float4* sp = (u < MTOT) ? (const float4*)na
                                  : (const float4*)(x + (size_t)r * DMODEL);

    float v[16];
    float s = 0.f, ss = 0.f;
#pragma unroll
    for (int q = 0; q < 4; q++) {
        float4 a = ap[lane + 32 * q];
        float4 st = sp[lane + 32 * q];
        float x0 = a.x + st.x, x1 = a.y + st.y, x2 = a.z + st.z, x3 = a.w + st.w;
        v[4 * q] = x0; v[4 * q + 1] = x1; v[4 * q + 2] = x2; v[4 * q + 3] = x3;
        s += x0 + x1 + x2 + x3;
        ss += x0 * x0 + x1 * x1 + x2 * x2 + x3 * x3;
    }
#pragma unroll
    for (int o = 16; o; o >>= 1) {
        s  += __shfl_xor_sync(0xffffffffu, s, o);
        ss += __shfl_xor_sync(0xffffffffu, ss, o);
    }
    const float mean = s * (1.f / DMODEL);
    const float var  = ss * (1.f / DMODEL) - mean * mean;
    const float inv  = rsqrtf(var + 1e-5f);

    const float4* gp = (const float4*)gamma;
    const float4* bp = (const float4*)beta;
    uint2* hp = (uint2*)(hh + (size_t)u * DMODEL);
    uint2* lp = (uint2*)(hl + (size_t)u * DMODEL);
#pragma unroll
    for (int q = 0; q < 4; q++) {
        float4 g = gp[lane + 32 * q], b = bp[lane + 32 * q];
        float o0 = (v[4 * q] - mean) * inv * g.x + b.x;
        float o1 = (v[4 * q + 1] - mean) * inv * g.y + b.y;
        float o2 = (v[4 * q + 2] - mean) * inv * g.z + b.z;
        float o3 = (v[4 * q + 3] - mean) * inv * g.w + b.w;
        __nv_bfloat16 h0 = __float2bfloat16_rn(o0), h1 = __float2bfloat16_rn(o1);
        __nv_bfloat16 h2 = __float2bfloat16_rn(o2), h3 = __float2bfloat16_rn(o3);
        __nv_bfloat162 ph0(h0, h1), ph1(h2, h3);
        __nv_bfloat162 pl0(__float2bfloat16_rn(o0 - __bfloat162float(h0)),
                           __float2bfloat16_rn(o1 - __bfloat162float(h1)));
        __nv_bfloat162 pl1(__float2bfloat16_rn(o2 - __bfloat162float(h2)),
                           __float2bfloat16_rn(o3 - __bfloat162float(h3)));
        hp[lane + 32 * q] = make_uint2(*(uint32_t*)&ph0, *(uint32_t*)&ph1);
        lp[lane + 32 * q] = make_uint2(*(uint32_t*)&pl0, *(uint32_t*)&pl1);
    }
}

// --------- per-row: max / 1/sumexp / candidate set from bf16 logits ---------
__device__ __forceinline__ float2 bf2f2(uint32_t w) {
    float2 r;
    r.x = __uint_as_float(w << 16);
    r.y = __uint_as_float(w & 0xffff0000u);
    return r;
}

__global__ __launch_bounds__(256) void reduce2_kernel(
    const __nv_bfloat16* __restrict__ logits, float* __restrict__ mOut,
    int* __restrict__ cnt, int* __restrict__ cand)
{
    __shared__ int scnt[8];
    const int warp = threadIdx.x >> 5, lane = threadIdx.x & 31;
    const int row = blockIdx.x * 8 + warp;
    const uint4* lp = (const uint4*)(logits + (size_t)row * NRELS);

    float vmax = -3.4e38f;
#pragma unroll
    for (int q = 0; q < 8; q++) {
        uint4 u = lp[lane + 32 * q];
        float2 a = bf2f2(u.x), b = bf2f2(u.y), c = bf2f2(u.z), d = bf2f2(u.w);
        vmax = fmaxf(vmax, fmaxf(fmaxf(fmaxf(a.x, a.y), fmaxf(b.x, b.y)),
                                 fmaxf(fmaxf(c.x, c.y), fmaxf(d.x, d.y))));
    }
#pragma unroll
    for (int o = 16; o; o >>= 1) vmax = fmaxf(vmax, __shfl_xor_sync(0xffffffffu, vmax, o));

    if (lane == 0) scnt[warp] = 0;
    __syncwarp();

    const float thr = vmax - 0.02f;
    float se = 0.f;
#pragma unroll
    for (int q = 0; q < 8; q++) {
        uint4 u = lp[lane + 32 * q];
        uint32_t ws[4] = {u.x, u.y, u.z, u.w};
        const int base = (lane + 32 * q) * 8;
#pragma unroll
        for (int wI = 0; wI < 4; wI++) {
            float2 e = bf2f2(ws[wI]);
            se += __expf(e.x - vmax) + __expf(e.y - vmax);
            if (e.x >= thr) {
                int p = atomicAdd(&scnt[warp], 1);
                if (p < CAND) cand[(size_t)row * CAND + p] = base + 2 * wI;
            }
            if (e.y >= thr) {
                int p = atomicAdd(&scnt[warp], 1);
                if (p < CAND) cand[(size_t)row * CAND + p] = base + 2 * wI + 1;
            }
        }
    }
#pragma unroll
    for (int o = 16; o; o >>= 1) se += __shfl_xor_sync(0xffffffffu, se, o);
    __syncwarp();
    if (lane == 0) { mOut[row] = 1.f / se; cnt[row] = scnt[warp]; }
}

// --------- exact fp32 rescue of the argmax among candidates ---------
__global__ __launch_bounds__(256) void rescue_kernel(
    const float* __restrict__ gact, const float* __restrict__ w2,
    const float* __restrict__ b2, const int* __restrict__ cnt,
    const int* __restrict__ cand, int* __restrict__ idxOut)
{
    const int warp = threadIdx.x >> 5, lane = threadIdx.x & 31;
    const int row = blockIdx.x * 8 + warp;
    const float4* g4 = (const float4*)(gact + (size_t)row * HID2);
    const int n = cnt[row];

    float best = -3.4e38f;
    int bi = 0x7fffffff;
    if (n <= CAND) {
        for (int t = 0; t < n; t++) {
            const int j = cand[(size_t)row * CAND + t];
            const float4* w4 = (const float4*)(w2 + (size_t)j * HID2);
            float s = 0.f;
#pragma unroll
            for (int k = lane; k < HID2 / 4; k += 32) {
                float4 wv = w4[k], gv = g4[k];
                s = fmaf(wv.x, gv.x, s); s = fmaf(wv.y, gv.y, s);
                s = fmaf(wv.z, gv.z, s); s = fmaf(wv.w, gv.w, s);
            }
#pragma unroll
            for (int o = 16; o; o >>= 1) s += __shfl_xor_sync(0xffffffffu, s, o);
            s += b2[j];
            if (s > best || (s == best && j < bi)) { best = s; bi = j; }
        }
    } else {
        for (int j = 0; j < NRELS; j++) {
            const float4* w4 = (const float4*)(w2 + (size_t)j * HID2);
            float s = 0.f;
            for (int k = lane; k < HID2 / 4; k += 32) {
                float4 wv = w4[k], gv = g4[k];
                s = fmaf(wv.x, gv.x, s); s = fmaf(wv.y, gv.y, s);
                s = fmaf(wv.z, gv.z, s); s = fmaf(wv.w, gv.w, s);
            }
#pragma unroll
            for (int o = 16; o; o >>= 1) s += __shfl_xor_sync(0xffffffffu, s, o);
            s += b2[j];
            if (s > best || (s == best && j < bi)) { best = s; bi = j; }
        }
    }
    if (lane == 0) idxOut[row] = bi;
}

// ---------------- final combine ----------------
__global__ void final_kernel(float* __restrict__ out)
{
    const int r = blockIdx.x * blockDim.x + threadIdx.x;
    if (r >= MTOT) return;
    const float m0 = g_m[r], m1 = g_m[MTOT + r];
    const int i0 = g_idx[r], i1 = g_idx[MTOT + r];
    const bool c0 = (i0 != 0) && (m0 >= 0.1f);
    const bool c1 = c0 && (i1 != 0) && (m1 >= 0.1f);
    const float score = c0 ? (c1 ? m0 * m1 : m0) : 0.f;
    out[r]            = score;
    out[MTOT + r]     = (float)i0;
    out[2 * MTOT + r] = (float)i1;
    out[3 * MTOT + r] = (float)((int)c0 + (int)c1);
}

// ---------------- launch ----------------
extern "C" void kernel_launch(void* const* d_in, const int* in_sizes, int n_in,
                              void* d_out, int out_size)
{
    const float* x    = (const float*)d_in[0];
    const float* na   = (const float*)d_in[1];
    const float* v_w  = (const float*)d_in[2];
    const float* v_b  = (const float*)d_in[3];
    const float* o_w  = (const float*)d_in[4];
    const float* o_b  = (const float*)d_in[5];
    const float* ln_g = (const float*)d_in[6];
    const float* ln_b = (const float*)d_in[7];
    const float* w1   = (const float*)d_in[8];
    const float* b1   = (const float*)d_in[9];
    const float* w2   = (const float*)d_in[10];
    const float* b2   = (const float*)d_in[11];
    float* out = (float*)d_out;

    float *Wc, *bc, *attn, *gactf, *m;
    __nv_bfloat16 *xh, *xl, *Wch, *Wcl, *w1h, *w1l, *w2b, *hh, *hl, *gactb, *logits;
    int *idx, *cnt, *cand;
    cudaGetSymbolAddress((void**)&Wc, g_Wc);
    cudaGetSymbolAddress((void**)&bc, g_bc);
    cudaGetSymbolAddress((void**)&xh, g_xh);
    cudaGetSymbolAddress((void**)&xl, g_xl);
    cudaGetSymbolAddress((void**)&Wch, g_Wch);
    cudaGetSymbolAddress((void**)&Wcl, g_Wcl);
    cudaGetSymbolAddress((void**)&w1h, g_w1h);
    cudaGetSymbolAddress((void**)&w1l, g_w1l);
    cudaGetSymbolAddress((void**)&w2b, g_w2b);
    cudaGetSymbolAddress((void**)&attn, g_attn);
    cudaGetSymbolAddress((void**)&hh, g_hh);
    cudaGetSymbolAddress((void**)&hl, g_hl);
    cudaGetSymbolAddress((void**)&gactf, g_gactf);
    cudaGetSymbolAddress((void**)&gactb, g_gactb);
    cudaGetSymbolAddress((void**)&logits, g_logits);
    cudaGetSymbolAddress((void**)&m, g_m);
    cudaGetSymbolAddress((void**)&idx, g_idx);
    cudaGetSymbolAddress((void**)&cnt, g_cnt);
    cudaGetSymbolAddress((void**)&cand, g_cand);

    cudaFuncSetAttribute(mma_gemm<0>, cudaFuncAttributeMaxDynamicSharedMemorySize, GSMEM);
    cudaFuncSetAttribute(mma_gemm<1>, cudaFuncAttributeMaxDynamicSharedMemorySize, GSMEM);
    cudaFuncSetAttribute(mma_gemm<2>, cudaFuncAttributeMaxDynamicSharedMemorySize, GSMEM);

    int nsm = 148;
    cudaDeviceGetAttribute(&nsm, cudaDevAttrMultiProcessorCount, 0);
    const int pgrid = 2 * nsm;      // persistent: 2 CTAs per SM

    // weight prep
    combine_w_kernel<<<dim3(32, 32), dim3(16, 16)>>>(o_w, v_w, Wc);
    combine_b_kernel<<<1, 512>>>(o_w, v_b, o_b, bc);
    split_kernel<<<(DMODEL * DMODEL / 4 + 255) / 256, 256>>>(Wc, Wch, Wcl, DMODEL * DMODEL / 4);
    split_kernel<<<(HID2 * DMODEL / 4 + 255) / 256, 256>>>(w1, w1h, w1l, HID2 * DMODEL / 4);
    round_kernel<<<(NRELS * HID2 / 4 + 255) / 256, 256>>>(w2, w2b, NRELS * HID2 / 4);
    split_kernel<<<(MTOT * DMODEL / 4 + 255) / 256, 256>>>(x, xh, xl, MTOT * DMODEL / 4);

    // attn = x @ Wc^T + bc   (3-term split: xh*wh + xh*wl + xl*wh)
    mma_gemm<0><<<pgrid, 256, GSMEM>>>(
        xh, xh, xl, xl, Wch, Wcl, Wch, Wcl, bc, attn, nullptr,
        DMODEL, DMODEL, DMODEL / 64, 3 * DMODEL / 64,
        DMODEL / 128, (DMODEL / 128) * (MTOT / 128));

    // LN for BOTH steps at once -> hh/hl [2*MTOT, D]
    ln_kernel<<<MB2 / 8, 256>>>(attn, na, x, ln_g, ln_b, hh, hl);

    // gact = relu(h @ w1^T + b1)  (3-term split) -> fp32 + bf16, M = 2*MTOT
    mma_gemm<1><<<pgrid, 256, GSMEM>>>(
        hh, hh, hl, hl, w1h, w1l, w1h, w1l, b1, gactf, gactb,
        HID2, DMODEL, DMODEL / 64, 3 * DMODEL / 64,
        HID2 / 128, (HID2 / 128) * (MB2 / 128));

    // logits = gact @ w2^T + b2  (1-pass bf16), M = 2*MTOT
    mma_gemm<2><<<pgrid, 256, GSMEM>>>(
        gactb, gactb, gactb, gactb, w2b, w2b, w2b, w2b, b2, nullptr, logits,
        NRELS, HID2, HID2 / 64, HID2 / 64,
        NRELS / 128, (NRELS / 128) * (MB2 / 128));

    reduce2_kernel<<<MB2 / 8, 256>>>(logits, m, cnt, cand);
    rescue_kernel<<<MB2 / 8, 256>>>(gactf, w2, b2, cnt, cand, idx);

    final_kernel<<<MTOT / 256, 256>>>(out);
}

// round 14
// speedup vs baseline: 1.7074x; 1.0077x over previous
#include <cuda_runtime.h>
#include <cuda_bf16.h>
#include <cuda_fp16.h>
#include <cstdint>

#define MTOT   32768
#define MB2    (2 * MTOT)
#define DMODEL 512
#define HID2   1024
#define NRELS  2048
#define CAND   32
#define STAGE_B 32768                 // A 128x64 (16KB) + B 128x64 (16KB)
#define GSMEM  (3 * STAGE_B)          // 3 stages = 96KB -> 2 CTAs/SM

// ---------------- scratch (static device globals; no allocs) ----------------
__device__ float          g_Wc[DMODEL * DMODEL];
__device__ float          g_bc[DMODEL];
__device__ __nv_bfloat16  g_xh[MTOT * DMODEL],  g_xl[MTOT * DMODEL];
__device__ __nv_bfloat16  g_Wch[DMODEL * DMODEL], g_Wcl[DMODEL * DMODEL];
__device__ __nv_bfloat16  g_w1h[HID2 * DMODEL],  g_w1l[HID2 * DMODEL];
__device__ __half         g_w2h[NRELS * HID2];
__device__ float          g_attn[MTOT * DMODEL];
__device__ __nv_bfloat16  g_hh[MB2 * DMODEL],  g_hl[MB2 * DMODEL];
__device__ float          g_gactf[MB2 * HID2];
__device__ __half         g_gacth[MB2 * HID2];
__device__ __nv_bfloat16  g_logits[MB2 * NRELS];
__device__ float          g_m[MB2];
__device__ int            g_idx[MB2];
__device__ int            g_cnt[MB2];
__device__ int            g_cand[MB2 * CAND];

// ---------------- PTX helpers (baseline ISA only) ----------------
__device__ __forceinline__ uint32_t smem_u32(const void* p) {
    uint32_t a;
    asm("{ .reg .u64 t; cvta.to.shared.u64 t, %1; cvt.u32.u64 %0, t; }" : "=r"(a) : "l"(p));
    return a;
}

#define CP_ASYNC16(sp, gp) \
    asm volatile("cp.async.cg.shared.global [%0], [%1], 16;\n" :: "r"(sp), "l"(gp) : "memory")
#define CP_COMMIT()   asm volatile("cp.async.commit_group;\n" ::: "memory")
#define CP_WAIT1()    asm volatile("cp.async.wait_group 1;\n" ::: "memory")

#define LDSM_X4(r, addr) \
    asm volatile("ldmatrix.sync.aligned.m8n8.x4.shared.b16 {%0,%1,%2,%3}, [%4];" \
        : "=r"((r)[0]), "=r"((r)[1]), "=r"((r)[2]), "=r"((r)[3]) : "r"(addr))

__device__ __forceinline__ void mma16816(float* c, const uint32_t* a, uint32_t b0, uint32_t b1) {
    asm volatile(
        "mma.sync.aligned.m16n8k16.row.col.f32.bf16.bf16.f32 "
        "{%0,%1,%2,%3},{%4,%5,%6,%7},{%8,%9},{%0,%1,%2,%3};\n"
        : "+f"(c[0]), "+f"(c[1]), "+f"(c[2]), "+f"(c[3])
        : "r"(a[0]), "r"(a[1]), "r"(a[2]), "r"(a[3]), "r"(b0), "r"(b1));
}

// fp16 x fp16 -> fp16 accumulate (D,C = 2 regs of f16x2)
__device__ __forceinline__ void mma16816h(uint32_t* c, const uint32_t* a, uint32_t b0, uint32_t b1) {
    asm volatile(
        "mma.sync.aligned.m16n8k16.row.col.f16.f16.f16.f16 "
        "{%0,%1},{%2,%3,%4,%5},{%6,%7},{%0,%1};\n"
        : "+r"(c[0]), "+r"(c[1])
        : "r"(a[0]), "r"(a[1]), "r"(a[2]), "r"(a[3]), "r"(b0), "r"(b1));
}

// ldmatrix address into a (rows x 64 elem16) tile (128B rows, xor-swizzled 16B chunks)
__device__ __forceinline__ uint32_t ldsm_addr(uint32_t base, int row0, int chunk0, int lane) {
    const int r = row0 + (lane & 15);
    const int c = chunk0 + (lane >> 4);
    return base + r * 128 + ((c ^ (r & 7)) << 4);
}

// ---------------- bf16 HMMA GEMM (persistent tiles) --------------------------
// C[M,N] = sum_reg A_reg @ B_reg^T (+bias). CTA 128x128, 8 warps, warp 64x32,
// K-tile 64, 3-stage depth-2 cp.async, grid-stride over tiles.
// EPI 0: Cf fp32      EPI 1: relu -> Cf fp32 AND Ch fp16
template <int EPI>
__global__ __launch_bounds__(256, 2) void mma_gemm(
    const __nv_bfloat16* __restrict__ A0, const __nv_bfloat16* __restrict__ A1,
    const __nv_bfloat16* __restrict__ A2,
    const __nv_bfloat16* __restrict__ B0, const __nv_bfloat16* __restrict__ B1,
    const __nv_bfloat16* __restrict__ B2,
    const float* __restrict__ bias, float* __restrict__ Cf, __half* __restrict__ Ch,
    int N, int Kreg, int kcpr, int nch, int ntx, int ntiles)
{
    extern __shared__ __align__(1024) char sm[];
    const int tid  = threadIdx.x;
    const int wid  = tid >> 5;
    const int lane = tid & 31;
    const int wm   = (wid >> 2) * 64;
    const int wn   = (wid & 3) * 32;
    const uint32_t sBase = smem_u32(sm);

    for (int t = blockIdx.x; t < ntiles; t += gridDim.x) {
        const int bm = (t / ntx) * 128;
        const int bn = (t % ntx) * 128;

        float acc[4][4][4];
#pragma unroll
        for (int i = 0; i < 4; i++)
#pragma unroll
            for (int j = 0; j < 4; j++)
#pragma unroll
                for (int k = 0; k < 4; k++) acc[i][j][k] = 0.f;

        auto load_tile = [&](int c, int stage) {
            const int reg = c / kcpr;
            const int kc  = c - reg * kcpr;
            const __nv_bfloat16* Ar = (reg == 0) ? A0 : (reg == 1) ? A1 : A2;
            const __nv_bfloat16* Br = (reg == 0) ? B0 : (reg == 1) ? B1 : B2;
            const uint32_t aBase = sBase + stage * STAGE_B;
            const uint32_t bBase = aBase + 16384;
#pragma unroll
            for (int i = 0; i < 4; i++) {
                const int u = tid + 256 * i;           // 0..1023 (128 rows x 8 chunks)
                const int r = u >> 3, ch = u & 7;
                const uint32_t soff = r * 128 + ((ch ^ (r & 7)) << 4);
                CP_ASYNC16(aBase + soff, Ar + (size_t)(bm + r) * Kreg + kc * 64 + ch * 8);
                CP_ASYNC16(bBase + soff, Br + (size_t)(bn + r) * Kreg + kc * 64 + ch * 8);
            }
        };

        __syncthreads();                 // all warps done with prev tile's smem
        load_tile(0, 0); CP_COMMIT();
        load_tile(1, 1); CP_COMMIT();

        int stage = 0;
        for (int c = 0; c < nch; c++) {
            CP_WAIT1();
            __syncthreads();
            if (c + 2 < nch) load_tile(c + 2, (c + 2) % 3);
            CP_COMMIT();

            const uint32_t aB = sBase + stage * STAGE_B;
            const uint32_t bB = aB + 16384;
#pragma unroll
            for (int kk = 0; kk < 4; kk++) {
                uint32_t ar[4][4], br[2][4];
#pragma unroll
                for (int mt = 0; mt < 4; mt++)
                    LDSM_X4(ar[mt], ldsm_addr(aB, wm + mt * 16, 2 * kk, lane));
#pragma unroll
                for (int nt = 0; nt < 2; nt++)
                    LDSM_X4(br[nt], ldsm_addr(bB, wn + nt * 16, 2 * kk, lane));
#pragma unroll
                for (int mt = 0; mt < 4; mt++)
#pragma unroll
                    for (int j = 0; j < 4; j++)
                        mma16816(acc[mt][j], ar[mt], br[j >> 1][j & 1], br[j >> 1][(j & 1) + 2]);
            }
            stage = (stage + 1) == 3 ? 0 : (stage + 1);
        }

        // ---- epilogue ----
        const int rbase = bm + wm + (lane >> 2);
        const int cbase = bn + wn + ((lane & 3) << 1);
#pragma unroll
        for (int mt = 0; mt < 4; mt++) {
#pragma unroll
            for (int j = 0; j < 4; j++) {
                const int row = rbase + mt * 16;
                const int col = cbase + j * 8;
                const float b0 = __ldg(&bias[col]), b1 = __ldg(&bias[col + 1]);
                float v0 = acc[mt][j][0] + b0, v1 = acc[mt][j][1] + b1;
                float v2 = acc[mt][j][2] + b0, v3 = acc[mt][j][3] + b1;
                if (EPI == 1) {
                    v0 = fmaxf(v0, 0.f); v1 = fmaxf(v1, 0.f);
                    v2 = fmaxf(v2, 0.f); v3 = fmaxf(v3, 0.f);
                }
                *(float2*)(Cf + (size_t)row * N + col)       = make_float2(v0, v1);
                *(float2*)(Cf + (size_t)(row + 8) * N + col) = make_float2(v2, v3);
                if (EPI == 1) {
                    *(__half2*)(Ch + (size_t)row * N + col)       = __floats2half2_rn(v0, v1);
                    *(__half2*)(Ch + (size_t)(row + 8) * N + col) = __floats2half2_rn(v2, v3);
                }
            }
        }
    }
}

// ---------------- fp16-acc HMMA GEMM (GEMM2: logits) -------------------------
// logits(bf16) = A(fp16) @ B(fp16)^T + bias, fp16 accumulate (double-rate probe)
__global__ __launch_bounds__(256, 2) void mma_gemm_h(
    const __half* __restrict__ A, const __half* __restrict__ B,
    const float* __restrict__ bias, __nv_bfloat16* __restrict__ Cb,
    int N, int K, int nch, int ntx, int ntiles)
{
    extern __shared__ __align__(1024) char sm[];
    const int tid  = threadIdx.x;
    const int wid  = tid >> 5;
    const int lane = tid & 31;
    const int wm   = (wid >> 2) * 64;
    const int wn   = (wid & 3) * 32;
    const uint32_t sBase = smem_u32(sm);

    for (int t = blockIdx.x; t < ntiles; t += gridDim.x) {
        const int bm = (t / ntx) * 128;
        const int bn = (t % ntx) * 128;

        uint32_t acc[4][4][2];
#pragma unroll
        for (int i = 0; i < 4; i++)
#pragma unroll
            for (int j = 0; j < 4; j++) { acc[i][j][0] = 0u; acc[i][j][1] = 0u; }

        auto load_tile = [&](int kc, int stage) {
            const uint32_t aBase = sBase + stage * STAGE_B;
            const uint32_t bBase = aBase + 16384;
#pragma unroll
            for (int i = 0; i < 4; i++) {
                const int u = tid + 256 * i;
                const int r = u >> 3, ch = u & 7;
                const uint32_t soff = r * 128 + ((ch ^ (r & 7)) << 4);
                CP_ASYNC16(aBase + soff, A + (size_t)(bm + r) * K + kc * 64 + ch * 8);
                CP_ASYNC16(bBase + soff, B + (size_t)(bn + r) * K + kc * 64 + ch * 8);
            }
        };

        __syncthreads();
        load_tile(0, 0); CP_COMMIT();
        load_tile(1, 1); CP_COMMIT();

        int stage = 0;
        for (int c = 0; c < nch; c++) {
            CP_WAIT1();
            __syncthreads();
            if (c + 2 < nch) load_tile(c + 2, (c + 2) % 3);
            CP_COMMIT();

            const uint32_t aB = sBase + stage * STAGE_B;
            const uint32_t bB = aB + 16384;
#pragma unroll
            for (int kk = 0; kk < 4; kk++) {
                uint32_t ar[4][4], br[2][4];
#pragma unroll
                for (int mt = 0; mt < 4; mt++)
                    LDSM_X4(ar[mt], ldsm_addr(aB, wm + mt * 16, 2 * kk, lane));
#pragma unroll
                for (int nt = 0; nt < 2; nt++)
                    LDSM_X4(br[nt], ldsm_addr(bB, wn + nt * 16, 2 * kk, lane));
#pragma unroll
                for (int mt = 0; mt < 4; mt++)
#pragma unroll
                    for (int j = 0; j < 4; j++)
                        mma16816h(acc[mt][j], ar[mt], br[j >> 1][j & 1], br[j >> 1][(j & 1) + 2]);
            }
            stage = (stage + 1) == 3 ? 0 : (stage + 1);
        }

        // ---- epilogue: f16 acc -> float + bias -> bf16 ----
        const int rbase = bm + wm + (lane >> 2);
        const int cbase = bn + wn + ((lane & 3) << 1);
#pragma unroll
        for (int mt = 0; mt < 4; mt++) {
#pragma unroll
            for (int j = 0; j < 4; j++) {
                const int row = rbase + mt * 16;
                const int col = cbase + j * 8;
                const float b0 = __ldg(&bias[col]), b1 = __ldg(&bias[col + 1]);
                float2 f0 = __half22float2(*(__half2*)&acc[mt][j][0]);
                float2 f1 = __half22float2(*(__half2*)&acc[mt][j][1]);
                float v0 = f0.x + b0, v1 = f0.y + b1;
                float v2 = f1.x + b0, v3 = f1.y + b1;
                *(__nv_bfloat162*)(Cb + (size_t)row * N + col)       = __floats2bfloat162_rn(v0, v1);
                *(__nv_bfloat162*)(Cb + (size_t)(row + 8) * N + col) = __floats2bfloat162_rn(v2, v3);
            }
        }
    }
}

// ---------------- small prep kernels ----------------
__global__ void combine_w_kernel(const float* __restrict__ ow, const float* __restrict__ vw,
                                 float* __restrict__ wc)
{
    __shared__ float As[16][16];
    __shared__ float Bs[16][17];
    const int tx = threadIdx.x, ty = threadIdx.y;
    const int i = blockIdx.y * 16 + ty;
    const int j = blockIdx.x * 16 + tx;
    float acc = 0.f;
    for (int k0 = 0; k0 < DMODEL; k0 += 16) {
        As[ty][tx] = ow[i * DMODEL + k0 + tx];
        Bs[ty][tx] = vw[(k0 + ty) * DMODEL + j];
        __syncthreads();
#pragma unroll
        for (int kk = 0; kk < 16; kk++) acc = fmaf(As[ty][kk], Bs[kk][tx], acc);
        __syncthreads();
    }
    wc[i * DMODEL + j] = acc;
}

__global__ void combine_b_kernel(const float* __restrict__ ow, const float* __restrict__ vb,
                                 const float* __restrict__ ob, float* __restrict__ bc)
{
    const int i = threadIdx.x;
    float acc = 0.f;
    for (int k = 0; k < DMODEL; k++) acc = fmaf(ow[i * DMODEL + k], vb[k], acc);
    bc[i] = acc + ob[i];
}

// fp32 -> (bf16 hi, bf16 lo) split, 4 elems / thread
__global__ void split_kernel(const float* __restrict__ in, __nv_bfloat16* __restrict__ hi,
                             __nv_bfloat16* __restrict__ lo, int n4)
{
    const int i = blockIdx.x * blockDim.x + threadIdx.x;
    if (i >= n4) return;
    float4 v = ((const float4*)in)[i];
    __nv_bfloat16 h0 = __float2bfloat16_rn(v.x), h1 = __float2bfloat16_rn(v.y);
    __nv_bfloat16 h2 = __float2bfloat16_rn(v.z), h3 = __float2bfloat16_rn(v.w);
    __nv_bfloat16 l0 = __float2bfloat16_rn(v.x - __bfloat162float(h0));
    __nv_bfloat16 l1 = __float2bfloat16_rn(v.y - __bfloat162float(h1));
    __nv_bfloat16 l2 = __float2bfloat16_rn(v.z - __bfloat162float(h2));
    __nv_bfloat16 l3 = __float2bfloat16_rn(v.w - __bfloat162float(h3));
    __nv_bfloat162* H = (__nv_bfloat162*)hi;
    __nv_bfloat162* L = (__nv_bfloat162*)lo;
    H[2 * i] = __nv_bfloat162(h0, h1); H[2 * i + 1] = __nv_bfloat162(h2, h3);
    L[2 * i] = __nv_bfloat162(l0, l1); L[2 * i + 1] = __nv_bfloat162(l2, l3);
}

// fp32 -> fp16 round, 4 elems / thread
__global__ void round_h_kernel(const float* __restrict__ in, __half* __restrict__ out, int n4)
{
    const int i = blockIdx.x * blockDim.x + threadIdx.x;
    if (i >= n4) return;
    float4 v = ((const float4*)in)[i];
    __half2* O = (__half2*)out;
    O[2 * i]     = __floats2half2_rn(v.x, v.y);
    O[2 * i + 1] = __floats2half2_rn(v.z, v.w);
}

// ------- LayerNorm(attn + state) -> split bf16 planes, BOTH steps batched ----
__global__ __launch_bounds__(256) void ln_kernel(
    const float* __restrict__ attn, const float* __restrict__ na, const float* __restrict__ x,
    const float* __restrict__ gamma, const float* __restrict__ beta,
    __nv_bfloat16* __restrict__ hh, __nv_bfloat16* __restrict__ hl)
{
    const int warp = threadIdx.x >> 5, lane = threadIdx.x & 31;
    const int u = blockIdx.x * 8 + warp;
    const int r = (u < MTOT) ? u : (u - MTOT);
    const float4* ap = (const float4*)(attn + (size_t)r * DMODEL);
    const float4* sp = (u < MTOT) ? (const float4*)na
                                  : (const float4*)(x + (size_t)r * DMODEL);

    float v[16];
    float s = 0.f, ss = 0.f;
#pragma unroll
    for (int q = 0; q < 4; q++) {
        float4 a = ap[lane + 32 * q];
        float4 st = sp[lane + 32 * q];
        float x0 = a.x + st.x, x1 = a.y + st.y, x2 = a.z + st.z, x3 = a.w + st.w;
        v[4 * q] = x0; v[4 * q + 1] = x1; v[4 * q + 2] = x2; v[4 * q + 3] = x3;
        s += x0 + x1 + x2 + x3;
        ss += x0 * x0 + x1 * x1 + x2 * x2 + x3 * x3;
    }
#pragma unroll
    for (int o = 16; o; o >>= 1) {
        s  += __shfl_xor_sync(0xffffffffu, s, o);
        ss += __shfl_xor_sync(0xffffffffu, ss, o);
    }
    const float mean = s * (1.f / DMODEL);
    const float var  = ss * (1.f / DMODEL) - mean * mean;
    const float inv  = rsqrtf(var + 1e-5f);

    const float4* gp = (const float4*)gamma;
    const float4* bp = (const float4*)beta;
    uint2* hp = (uint2*)(hh + (size_t)u * DMODEL);
    uint2* lp = (uint2*)(hl + (size_t)u * DMODEL);
#pragma unroll
    for (int q = 0; q < 4; q++) {
        float4 g = gp[lane + 32 * q], b = bp[lane + 32 * q];
        float o0 = (v[4 * q] - mean) * inv * g.x + b.x;
        float o1 = (v[4 * q + 1] - mean) * inv * g.y + b.y;
        float o2 = (v[4 * q + 2] - mean) * inv * g.z + b.z;
        float o3 = (v[4 * q + 3] - mean) * inv * g.w + b.w;
        __nv_bfloat16 h0 = __float2bfloat16_rn(o0), h1 = __float2bfloat16_rn(o1);
        __nv_bfloat16 h2 = __float2bfloat16_rn(o2), h3 = __float2bfloat16_rn(o3);
        __nv_bfloat162 ph0(h0, h1), ph1(h2, h3);
        __nv_bfloat162 pl0(__float2bfloat16_rn(o0 - __bfloat162float(h0)),
                           __float2bfloat16_rn(o1 - __bfloat162float(h1)));
        __nv_bfloat162 pl1(__float2bfloat16_rn(o2 - __bfloat162float(h2)),
                           __float2bfloat16_rn(o3 - __bfloat162float(h3)));
        hp[lane + 32 * q] = make_uint2(*(uint32_t*)&ph0, *(uint32_t*)&ph1);
        lp[lane + 32 * q] = make_uint2(*(uint32_t*)&pl0, *(uint32_t*)&pl1);
    }
}

// --------- per-row: max / 1/sumexp / candidate set from bf16 logits ---------
__device__ __forceinline__ float2 bf2f2(uint32_t w) {
    float2 r;
    r.x = __uint_as_float(w << 16);
    r.y = __uint_as_float(w & 0xffff0000u);
    return r;
}

__global__ __launch_bounds__(256) void reduce2_kernel(
    const __nv_bfloat16* __restrict__ logits, float* __restrict__ mOut,
    int* __restrict__ cnt, int* __restrict__ cand)
{
    __shared__ int scnt[8];
    const int warp = threadIdx.x >> 5, lane = threadIdx.x & 31;
    const int row = blockIdx.x * 8 + warp;
    const uint4* lp = (const uint4*)(logits + (size_t)row * NRELS);

    float vmax = -3.4e38f;
#pragma unroll
    for (int q = 0; q < 8; q++) {
        uint4 u = lp[lane + 32 * q];
        float2 a = bf2f2(u.x), b = bf2f2(u.y), c = bf2f2(u.z), d = bf2f2(u.w);
        vmax = fmaxf(vmax, fmaxf(fmaxf(fmaxf(a.x, a.y), fmaxf(b.x, b.y)),
                                 fmaxf(fmaxf(c.x, c.y), fmaxf(d.x, d.y))));
    }
#pragma unroll
    for (int o = 16; o; o >>= 1) vmax = fmaxf(vmax, __shfl_xor_sync(0xffffffffu, vmax, o));

    if (lane == 0) scnt[warp] = 0;
    __syncwarp();

    const float thr = vmax - 0.05f;      // covers fp16-accumulate noise (sigma ~1-3e-3)
    float se = 0.f;
#pragma unroll
    for (int q = 0; q < 8; q++) {
        uint4 u = lp[lane + 32 * q];
        uint32_t ws[4] = {u.x, u.y, u.z, u.w};
        const int base = (lane + 32 * q) * 8;
#pragma unroll
        for (int wI = 0; wI < 4; wI++) {
            float2 e = bf2f2(ws[wI]);
            se += __expf(e.x - vmax) + __expf(e.y - vmax);
            if (e.x >= thr) {
                int p = atomicAdd(&scnt[warp], 1);
                if (p < CAND) cand[(size_t)row * CAND + p] = base + 2 * wI;
            }
            if (e.y >= thr) {
                int p = atomicAdd(&scnt[warp], 1);
                if (p < CAND) cand[(size_t)row * CAND + p] = base + 2 * wI + 1;
            }
        }
    }
#pragma unroll
    for (int o = 16; o; o >>= 1) se += __shfl_xor_sync(0xffffffffu, se, o);
    __syncwarp();
    if (lane == 0) { mOut[row] = 1.f / se; cnt[row] = scnt[warp]; }
}

// --------- exact fp32 rescue of the argmax among candidates ---------
__global__ __launch_bounds__(256) void rescue_kernel(
    const float* __restrict__ gact, const float* __restrict__ w2,
    const float* __restrict__ b2, const int* __restrict__ cnt,
    const int* __restrict__ cand, int* __restrict__ idxOut)
{
    const int warp = threadIdx.x >> 5, lane = threadIdx.x & 31;
    const int row = blockIdx.x * 8 + warp;
    const float4* g4 = (const float4*)(gact + (size_t)row * HID2);
    const int n = cnt[row];

    float best = -3.4e38f;
    int bi = 0x7fffffff;
    if (n <= CAND) {
        for (int t = 0; t < n; t++) {
            const int j = cand[(size_t)row * CAND + t];
            const float4* w4 = (const float4*)(w2 + (size_t)j * HID2);
            float s = 0.f;
#pragma unroll
            for (int k = lane; k < HID2 / 4; k += 32) {
                float4 wv = w4[k], gv = g4[k];
                s = fmaf(wv.x, gv.x, s); s = fmaf(wv.y, gv.y, s);
                s = fmaf(wv.z, gv.z, s); s = fmaf(wv.w, gv.w, s);
            }
#pragma unroll
            for (int o = 16; o; o >>= 1) s += __shfl_xor_sync(0xffffffffu, s, o);
            s += b2[j];
            if (s > best || (s == best && j < bi)) { best = s; bi = j; }
        }
    } else {
        for (int j = 0; j < NRELS; j++) {
            const float4* w4 = (const float4*)(w2 + (size_t)j * HID2);
            float s = 0.f;
            for (int k = lane; k < HID2 / 4; k += 32) {
                float4 wv = w4[k], gv = g4[k];
                s = fmaf(wv.x, gv.x, s); s = fmaf(wv.y, gv.y, s);
                s = fmaf(wv.z, gv.z, s); s = fmaf(wv.w, gv.w, s);
            }
#pragma unroll
            for (int o = 16; o; o >>= 1) s += __shfl_xor_sync(0xffffffffu, s, o);
            s += b2[j];
            if (s > best || (s == best && j < bi)) { best = s; bi = j; }
        }
    }
    if (lane == 0) idxOut[row] = bi;
}

// ---------------- final combine ----------------
__global__ void final_kernel(float* __restrict__ out)
{
    const int r = blockIdx.x * blockDim.x + threadIdx.x;
    if (r >= MTOT) return;
    const float m0 = g_m[r], m1 = g_m[MTOT + r];
    const int i0 = g_idx[r], i1 = g_idx[MTOT + r];
    const bool c0 = (i0 != 0) && (m0 >= 0.1f);
    const bool c1 = c0 && (i1 != 0) && (m1 >= 0.1f);
    const float score = c0 ? (c1 ? m0 * m1 : m0) : 0.f;
    out[r]            = score;
    out[MTOT + r]     = (float)i0;
    out[2 * MTOT + r] = (float)i1;
    out[3 * MTOT + r] = (float)((int)c0 + (int)c1);
}

// ---------------- launch ----------------
extern "C" void kernel_launch(void* const* d_in, const int* in_sizes, int n_in,
                              void* d_out, int out_size)
{
    const float* x    = (const float*)d_in[0];
    const float* na   = (const float*)d_in[1];
    const float* v_w  = (const float*)d_in[2];
    const float* v_b  = (const float*)d_in[3];
    const float* o_w  = (const float*)d_in[4];
    const float* o_b  = (const float*)d_in[5];
    const float* ln_g = (const float*)d_in[6];
    const float* ln_b = (const float*)d_in[7];
    const float* w1   = (const float*)d_in[8];
    const float* b1   = (const float*)d_in[9];
    const float* w2   = (const float*)d_in[10];
    const float* b2   = (const float*)d_in[11];
    float* out = (float*)d_out;

    float *Wc, *bc, *attn, *gactf, *m;
    __nv_bfloat16 *xh, *xl, *Wch, *Wcl, *w1h, *w1l, *hh, *hl, *logits;
    __half *gacth, *w2h;
    int *idx, *cnt, *cand;
    cudaGetSymbolAddress((void**)&Wc, g_Wc);
    cudaGetSymbolAddress((void**)&bc, g_bc);
    cudaGetSymbolAddress((void**)&xh, g_xh);
    cudaGetSymbolAddress((void**)&xl, g_xl);
    cudaGetSymbolAddress((void**)&Wch, g_Wch);
    cudaGetSymbolAddress((void**)&Wcl, g_Wcl);
    cudaGetSymbolAddress((void**)&w1h, g_w1h);
    cudaGetSymbolAddress((void**)&w1l, g_w1l);
    cudaGetSymbolAddress((void**)&w2h, g_w2h);
    cudaGetSymbolAddress((void**)&attn, g_attn);
    cudaGetSymbolAddress((void**)&hh, g_hh);
    cudaGetSymbolAddress((void**)&hl, g_hl);
    cudaGetSymbolAddress((void**)&gactf, g_gactf);
    cudaGetSymbolAddress((void**)&gacth, g_gacth);
    cudaGetSymbolAddress((void**)&logits, g_logits);
    cudaGetSymbolAddress((void**)&m, g_m);
    cudaGetSymbolAddress((void**)&idx, g_idx);
    cudaGetSymbolAddress((void**)&cnt, g_cnt);
    cudaGetSymbolAddress((void**)&cand, g_cand);

    cudaFuncSetAttribute(mma_gemm<0>, cudaFuncAttributeMaxDynamicSharedMemorySize, GSMEM);
    cudaFuncSetAttribute(mma_gemm<1>, cudaFuncAttributeMaxDynamicSharedMemorySize, GSMEM);
    cudaFuncSetAttribute(mma_gemm_h, cudaFuncAttributeMaxDynamicSharedMemorySize, GSMEM);

    int nsm = 148;
    cudaDeviceGetAttribute(&nsm, cudaDevAttrMultiProcessorCount, 0);
    const int pgrid = 2 * nsm;      // persistent: 2 CTAs per SM

    // weight prep
    combine_w_kernel<<<dim3(32, 32), dim3(16, 16)>>>(o_w, v_w, Wc);
    combine_b_kernel<<<1, 512>>>(o_w, v_b, o_b, bc);
    split_kernel<<<(DMODEL * DMODEL / 4 + 255) / 256, 256>>>(Wc, Wch, Wcl, DMODEL * DMODEL / 4);
    split_kernel<<<(HID2 * DMODEL / 4 + 255) / 256, 256>>>(w1, w1h, w1l, HID2 * DMODEL / 4);
    round_h_kernel<<<(NRELS * HID2 / 4 + 255) / 256, 256>>>(w2, w2h, NRELS * HID2 / 4);
    split_kernel<<<(MTOT * DMODEL / 4 + 255) / 256, 256>>>(x, xh, xl, MTOT * DMODEL / 4);

    // attn = x @ Wc^T + bc   (3-term split: xh*wh + xh*wl + xl*wh)
    mma_gemm<0><<<pgrid, 256, GSMEM>>>(
        xh, xh, xl, Wch, Wcl, Wch, bc, attn, nullptr,
        DMODEL, DMODEL, DMODEL / 64, 3 * DMODEL / 64,
        DMODEL / 128, (DMODEL / 128) * (MTOT / 128));

    // LN for BOTH steps at once -> hh/hl [2*MTOT, D]
    ln_kernel<<<MB2 / 8, 256>>>(attn, na, x, ln_g, ln_b, hh, hl);

    // gact = relu(h @ w1^T + b1)  (3-term split) -> fp32 + fp16, M = 2*MTOT
    mma_gemm<1><<<pgrid, 256, GSMEM>>>(
        hh, hh, hl, w1h, w1l, w1h, b1, gactf, gacth,
        HID2, DMODEL, DMODEL / 64, 3 * DMODEL / 64,
        HID2 / 128, (HID2 / 128) * (MB2 / 128));

    // logits = gact @ w2^T + b2  (1-pass fp16, fp16 accumulate), M = 2*MTOT
    mma_gemm_h<<<pgrid, 256, GSMEM>>>(
        gacth, w2h, b2, logits,
        NRELS, HID2, HID2 / 64,
        NRELS / 128, (NRELS / 128) * (MB2 / 128));

    reduce2_kernel<<<MB2 / 8, 256>>>(logits, m, cnt, cand);
    rescue_kernel<<<MB2 / 8, 256>>>(gactf, w2, b2, cnt, cand, idx);

    final_kernel<<<MTOT / 256, 256>>>(out);
}